// round 12
// baseline (speedup 1.0000x reference)
#include <cuda_runtime.h>
#include <math.h>

// Problem constants
#define BQ   2
#define TT   4096
#define CC   2048
#define DD   64
#define MTOK (BQ*TT)      // 8192 tokens
#define LCH  32
#define NCH  (TT/LCH)     // 128 chunks per batch

// ---------------- device scratch ----------------
__device__ __align__(16) float g_y [MTOK*160];       // tanh mix features (tf32-rounded)
__device__ __align__(16) float g_r [MTOK*DD];
__device__ __align__(16) float g_k [MTOK*DD];
__device__ __align__(16) float g_v [MTOK*DD];
__device__ __align__(16) float g_gv[MTOK*DD];
__device__ __align__(16) float g_w [MTOK*DD];
__device__ __align__(16) float g_M [BQ*NCH*DD*DD];
__device__ __align__(16) float g_S [BQ*NCH*DD*DD];
__device__ __align__(16) float g_P [BQ*NCH*DD];
__device__ __align__(16) float g_o [MTOK*DD];

// ---------------- tf32 mma helpers ----------------
__device__ __forceinline__ float tf32r(float x) {
    unsigned u;
    asm("cvt.rna.tf32.f32 %0, %1;" : "=r"(u) : "f"(x));
    return __uint_as_float(u);
}
__device__ __forceinline__ void mma8(float* d,
    unsigned a0, unsigned a1, unsigned a2, unsigned a3,
    unsigned b0, unsigned b1)
{
    asm volatile(
        "mma.sync.aligned.m16n8k8.row.col.f32.tf32.tf32.f32 "
        "{%0,%1,%2,%3}, {%4,%5,%6,%7}, {%8,%9}, {%0,%1,%2,%3};"
        : "+f"(d[0]), "+f"(d[1]), "+f"(d[2]), "+f"(d[3])
        : "r"(a0), "r"(a1), "r"(a2), "r"(a3), "r"(b0), "r"(b1));
}
#define FB(x) __float_as_uint(x)

// =====================================================================
// K1 (proven v2, now launched as two half-grids): y = tanh( x @ w1 )
// =====================================================================
__global__ __launch_bounds__(256) void k1_mix(
    const float* __restrict__ hs, const float* __restrict__ shift,
    const float* __restrict__ maa_x, const float* __restrict__ w1,
    int blk0)
{
    __shared__ float x_s [32*36];
    __shared__ float w1_s[32*168];
    const int tid  = threadIdx.x;
    const int lane = tid & 31, wid = tid >> 5;
    const int gi   = lane >> 2, t = lane & 3;
    const int m0   = (blockIdx.x + blk0) * 32;
    const int mt   = wid & 1;
    const int ng   = wid >> 1;

    float acc[5][4];
    #pragma unroll
    for (int j = 0; j < 5; j++)
        #pragma unroll
        for (int e = 0; e < 4; e++) acc[j][e] = 0.f;

    float px[4], pw[20];
    #pragma unroll
    for (int u = 0; u < 4; u++) {
        int idx = tid + 256*u, i = idx >> 5, kk = idx & 31;
        int m = m0 + i, c = kk;
        float cur  = hs[(size_t)m*CC + c];
        float prev = ((m & (TT-1)) == 0) ? shift[(m>>12)*CC + c]
                                         : hs[(size_t)(m-1)*CC + c];
        px[u] = tf32r(cur + (prev - cur) * __ldg(&maa_x[c]));
    }
    #pragma unroll
    for (int u = 0; u < 20; u++) {
        int idx = tid + 256*u, kk = idx/160, n = idx - kk*160;
        pw[u] = tf32r(w1[(size_t)kk*160 + n]);
    }

    for (int k0 = 0; k0 < CC; k0 += 32) {
        __syncthreads();
        #pragma unroll
        for (int u = 0; u < 4; u++) {
            int idx = tid + 256*u;
            x_s[(idx >> 5)*36 + (idx & 31)] = px[u];
        }
        #pragma unroll
        for (int u = 0; u < 20; u++) {
            int idx = tid + 256*u, kk = idx/160, n = idx - kk*160;
            w1_s[kk*168 + n] = pw[u];
        }
        __syncthreads();
        const int kn = k0 + 32;
        if (kn < CC) {
            #pragma unroll
            for (int u = 0; u < 4; u++) {
                int idx = tid + 256*u, i = idx >> 5, kk = idx & 31;
                int m = m0 + i, c = kn + kk;
                float cur  = hs[(size_t)m*CC + c];
                float prev = ((m & (TT-1)) == 0) ? shift[(m>>12)*CC + c]
                                                 : hs[(size_t)(m-1)*CC + c];
                px[u] = tf32r(cur + (prev - cur) * __ldg(&maa_x[c]));
            }
            #pragma unroll
            for (int u = 0; u < 20; u++) {
                int idx = tid + 256*u, kk = idx/160, n = idx - kk*160;
                pw[u] = tf32r(w1[(size_t)(kn+kk)*160 + n]);
            }
        }
        #pragma unroll
        for (int ks = 0; ks < 4; ks++) {
            const float* Ab = x_s + (mt*16)*36 + ks*8;
            unsigned a0 = FB(Ab[gi*36 + t]);
            unsigned a1 = FB(Ab[(gi+8)*36 + t]);
            unsigned a2 = FB(Ab[gi*36 + t + 4]);
            unsigned a3 = FB(Ab[(gi+8)*36 + t + 4]);
            #pragma unroll
            for (int j = 0; j < 5; j++) {
                int n0 = ng*40 + j*8;
                unsigned b0 = FB(w1_s[(ks*8+t)*168 + n0 + gi]);
                unsigned b1 = FB(w1_s[(ks*8+t+4)*168 + n0 + gi]);
                mma8(acc[j], a0,a1,a2,a3, b0,b1);
            }
        }
    }
    const int mrow = m0 + mt*16 + gi;
    #pragma unroll
    for (int j = 0; j < 5; j++) {
        int n = ng*40 + j*8 + t*2;
        g_y[(size_t)mrow*160 + n]       = tf32r(tanhf(acc[j][0]));
        g_y[(size_t)mrow*160 + n + 1]   = tf32r(tanhf(acc[j][1]));
        g_y[(size_t)(mrow+8)*160 + n]   = tf32r(tanhf(acc[j][2]));
        g_y[(size_t)(mrow+8)*160 + n+1] = tf32r(tanhf(acc[j][3]));
    }
}

// =====================================================================
// K7 (standalone again): lx = hs[:, -1, :]
// =====================================================================
__global__ void k7_lx(const float* __restrict__ hs, float* __restrict__ out_lx)
{
    int idx = blockIdx.x*blockDim.x + threadIdx.x;   // B*C = 4096
    int b = idx >> 11, c = idx & 2047;
    out_lx[idx] = hs[((size_t)b*TT + (TT-1))*CC + c];
}

// =====================================================================
// KP (R11-proven, unchanged): per (128 tokens, one field f) with folded
// decay GEMM in the f==0 epilogue. NOW AT LAUNCH INDEX 3 (ncu target).
// =====================================================================
#define KP_Y   (128*36)
#define KP_HS  (129*36)
#define KP_ST  (128*36)
#define KP_W2  (32*40)
#define KP_W   (32*72)
#define KP_SMEM_FLOATS (KP_Y + KP_HS + KP_ST + KP_W2 + KP_W + 32)
#define KP_SMEM_BYTES  (KP_SMEM_FLOATS*4)

__global__ __launch_bounds__(256) void kp_proj(
    const float* __restrict__ hs, const float* __restrict__ shift,
    const float* __restrict__ maa_w, const float* __restrict__ maa_k,
    const float* __restrict__ maa_v, const float* __restrict__ maa_r,
    const float* __restrict__ maa_g, const float* __restrict__ w2,
    const float* __restrict__ dw1,  const float* __restrict__ Wk,
    const float* __restrict__ Wv,   const float* __restrict__ Wr,
    const float* __restrict__ Wg,   const float* __restrict__ dw2,
    const float* __restrict__ tdecay)
{
    extern __shared__ float sm[];
    float* y_s   = sm;               // [128][36]
    float* hs_s  = y_s  + KP_Y;      // [129][36] row i <-> token m0-1+i
    float* st_s  = hs_s + KP_HS;     // [128][36] A staging
    float* w2_s  = st_s + KP_ST;     // [32][40]  [d][c]
    float* W_s   = w2_s + KP_W2;     // [32][72]  [kk][n]
    float* maa_s = W_s  + KP_W;      // [32]

    const int tid  = threadIdx.x;
    const int lane = tid & 31, wid = tid >> 5;   // 8 warps, warp = 16-token tile
    const int gi   = lane >> 2, t = lane & 3;
    const int m0   = blockIdx.x * 128;
    const int f    = blockIdx.y;

    const float* mp = (f==0) ? maa_w : (f==1) ? maa_k : (f==2) ? maa_v
                     : (f==3) ? maa_r : maa_g;
    const float* Wf = (f==0) ? dw1 : (f==1) ? Wk : (f==2) ? Wv
                     : (f==3) ? Wr : Wg;

    // stage y_f slice once (row = 128B, coalesced)
    for (int idx = tid; idx < 128*32; idx += 256) {
        int i = idx >> 5, kk = idx & 31;
        y_s[i*36 + kk] = g_y[(size_t)(m0+i)*160 + f*32 + kk];
    }

    float acc[8][4];
    #pragma unroll
    for (int j = 0; j < 8; j++)
        #pragma unroll
        for (int e = 0; e < 4; e++) acc[j][e] = 0.f;

    for (int c0 = 0; c0 < CC; c0 += 32) {
        __syncthreads();   // prev chunk consumed (covers y_s stage before 1st use)
        for (int idx = tid; idx < 129*32; idx += 256) {
            int i = idx >> 5, c = idx & 31;
            float v;
            if (i == 0 && (m0 & (TT-1)) == 0)
                v = shift[(m0 >> 12)*CC + c0 + c];
            else
                v = hs[(size_t)(m0 - 1 + i)*CC + c0 + c];
            hs_s[i*36 + c] = v;
        }
        for (int idx = tid; idx < 1024; idx += 256) {
            int d = idx >> 5, c = idx & 31;
            w2_s[d*40 + c] = tf32r(w2[(size_t)(f*32 + d)*CC + c0 + c]);
        }
        for (int idx = tid; idx < 2048; idx += 256) {
            int kk = idx >> 6, n = idx & 63;
            W_s[kk*72 + n] = tf32r(Wf[(size_t)(c0+kk)*64 + n]);
        }
        if (tid < 32) maa_s[tid] = mp[c0 + tid];
        __syncthreads();

        // phase A: m(16x32 per warp) = y(16x32) @ w2(32x32)
        float accA[4][4];
        #pragma unroll
        for (int j = 0; j < 4; j++)
            #pragma unroll
            for (int e = 0; e < 4; e++) accA[j][e] = 0.f;
        #pragma unroll
        for (int ks = 0; ks < 4; ks++) {
            const float* Ab = y_s + (wid*16)*36 + ks*8;
            unsigned a0 = FB(Ab[gi*36 + t]);
            unsigned a1 = FB(Ab[(gi+8)*36 + t]);
            unsigned a2 = FB(Ab[gi*36 + t + 4]);
            unsigned a3 = FB(Ab[(gi+8)*36 + t + 4]);
            #pragma unroll
            for (int j = 0; j < 4; j++) {
                unsigned b0 = FB(w2_s[(ks*8+t)*40   + j*8 + gi]);
                unsigned b1 = FB(w2_s[(ks*8+t+4)*40 + j*8 + gi]);
                mma8(accA[j], a0,a1,a2,a3, b0,b1);
            }
        }
        // build A rows wid*16..+15 (warp-local)
        #pragma unroll
        for (int j = 0; j < 4; j++) {
            #pragma unroll
            for (int e = 0; e < 4; e++) {
                int r = wid*16 + gi + ((e & 2) ? 8 : 0);
                int c = j*8 + t*2 + (e & 1);
                float cur  = hs_s[(r+1)*36 + c];
                float prev = hs_s[r*36 + c];
                st_s[r*36 + c] = tf32r(cur + (prev - cur)*(maa_s[c] + accA[j][e]));
            }
        }
        __syncwarp();   // cross-lane visibility of st_s within the warp

        // phase B: acc(16x64) += A(16x32) @ W(32x64); same warp-local rows
        #pragma unroll
        for (int ks = 0; ks < 4; ks++) {
            const float* Ab = st_s + (wid*16)*36 + ks*8;
            unsigned a0 = FB(Ab[gi*36 + t]);
            unsigned a1 = FB(Ab[(gi+8)*36 + t]);
            unsigned a2 = FB(Ab[gi*36 + t + 4]);
            unsigned a3 = FB(Ab[(gi+8)*36 + t + 4]);
            #pragma unroll
            for (int j = 0; j < 8; j++) {
                unsigned b0 = FB(W_s[(ks*8+t)*72   + j*8 + gi]);
                unsigned b1 = FB(W_s[(ks*8+t+4)*72 + j*8 + gi]);
                mma8(acc[j], a0,a1,a2,a3, b0,b1);
            }
        }
    }

    if (f != 0) {
        #pragma unroll
        for (int j = 0; j < 8; j++) {
            #pragma unroll
            for (int e = 0; e < 4; e++) {
                int m = m0 + wid*16 + gi + ((e & 2) ? 8 : 0);
                int n = j*8 + t*2 + (e & 1);
                size_t ad = (size_t)m*64 + n;
                float x = acc[j][e];
                if      (f == 1) g_k[ad] = x;
                else if (f == 2) g_v[ad] = x;
                else if (f == 3) g_r[ad] = x;
                else             g_gv[ad] = x / (1.f + expf(-x));
            }
        }
    } else {
        // folded decay path: T = tf32(tanh(acc)); g_w = -exp(tdecay + T@dw2)
        __syncthreads();                 // all warps done with y_s/hs_s/st_s
        float* T_s  = sm;                // [128][68] aliases y_s+hs_s
        float* d2_s = st_s;              // [64][72] exact fit
        float* td_s = W_s;               // [64]
        #pragma unroll
        for (int j = 0; j < 8; j++) {
            #pragma unroll
            for (int e = 0; e < 4; e++) {
                int r = wid*16 + gi + ((e & 2) ? 8 : 0);
                int c = j*8 + t*2 + (e & 1);
                T_s[r*68 + c] = tf32r(tanhf(acc[j][e]));
            }
        }
        for (int idx = tid; idx < 4096; idx += 256) {
            int d = idx >> 6, n = idx & 63;
            d2_s[d*72 + n] = tf32r(dw2[idx]);
        }
        if (tid < 64) td_s[tid] = tdecay[tid];
        __syncthreads();

        float acc2[8][4];
        #pragma unroll
        for (int j = 0; j < 8; j++)
            #pragma unroll
            for (int e = 0; e < 4; e++) acc2[j][e] = 0.f;
        #pragma unroll
        for (int ks = 0; ks < 8; ks++) {
            const float* Ab = T_s + (wid*16)*68 + ks*8;
            unsigned a0 = FB(Ab[gi*68 + t]);
            unsigned a1 = FB(Ab[(gi+8)*68 + t]);
            unsigned a2 = FB(Ab[gi*68 + t + 4]);
            unsigned a3 = FB(Ab[(gi+8)*68 + t + 4]);
            #pragma unroll
            for (int j = 0; j < 8; j++) {
                unsigned b0 = FB(d2_s[(ks*8+t)*72 + j*8 + gi]);
                unsigned b1 = FB(d2_s[(ks*8+t+4)*72 + j*8 + gi]);
                mma8(acc2[j], a0,a1,a2,a3, b0,b1);
            }
        }
        #pragma unroll
        for (int j = 0; j < 8; j++) {
            #pragma unroll
            for (int e = 0; e < 4; e++) {
                int m = m0 + wid*16 + gi + ((e & 2) ? 8 : 0);
                int n = j*8 + t*2 + (e & 1);
                g_w[(size_t)m*64 + n] = -expf(td_s[n] + acc2[j][e]);
            }
        }
    }
}

// =====================================================================
// K3 (proven)
// =====================================================================
__global__ __launch_bounds__(256,1) void k3_chunk()
{
    __shared__ float k_s[32*64], v_s[32*64], cum_s[32*64], kh_s[32*64];
    const int bc   = blockIdx.x;
    const int tok0 = bc * 32;
    const int tid  = threadIdx.x;

    for (int idx = tid; idx < 2048; idx += 256) {
        size_t g = (size_t)tok0*64 + idx;
        k_s[idx]   = g_k[g];
        v_s[idx]   = g_v[g];
        cum_s[idx] = g_w[g];
    }
    __syncthreads();
    if (tid < 64) {
        float c = 0.f;
        for (int i = 0; i < 32; i++) { c += cum_s[i*64 + tid]; cum_s[i*64 + tid] = c; }
        g_P[bc*64 + tid] = expf(c);
        for (int i = 0; i < 32; i++)
            kh_s[i*64 + tid] = k_s[i*64 + tid] * expf(c - cum_s[i*64 + tid]);
    }
    __syncthreads();
    for (int it = 0; it < 16; it++) {
        int e  = tid + 256*it;
        int dk = e >> 6, dv = e & 63;
        float s = 0.f;
        #pragma unroll
        for (int i = 0; i < 32; i++)
            s += kh_s[i*64 + dk] * v_s[i*64 + dv];
        g_M[(size_t)bc*4096 + e] = s;
    }
}

// =====================================================================
// K4 (proven, R9 form): inter-chunk scan, prefetch depth 32
// =====================================================================
__global__ __launch_bounds__(256,1) void k4_scan(
    const float* __restrict__ wkv0, float* __restrict__ out_sf)
{
    const int e  = blockIdx.x*256 + threadIdx.x;
    const int b  = e >> 12, eb = e & 4095, dk = eb >> 6;
    float sv = wkv0[e];
    const float* Mp = g_M + (size_t)b*NCH*4096 + eb;
    const float* Pp = g_P + b*NCH*64 + dk;
    float*       Sp = g_S + (size_t)b*NCH*4096 + eb;

    float mq[32], pq[32];
    #pragma unroll
    for (int q = 0; q < 32; q++) { mq[q] = Mp[(size_t)q*4096]; pq[q] = Pp[q*64]; }

    for (int c = 0; c < NCH; c += 32) {
        #pragma unroll
        for (int q = 0; q < 32; q++) {
            Sp[(size_t)(c+q)*4096] = sv;
            sv = sv*pq[q] + mq[q];
            int cn = c + q + 32;
            if (cn < NCH) { mq[q] = Mp[(size_t)cn*4096]; pq[q] = Pp[cn*64]; }
        }
    }
    out_sf[e] = sv;
}

// =====================================================================
// K5 (proven)
// =====================================================================
#define K5_SMEM_FLOATS (4*(32*65) + 64*65 + 32*33 + 32)
#define K5_SMEM_BYTES  (K5_SMEM_FLOATS*4)

__global__ __launch_bounds__(256,1) void k5_intra(const float* __restrict__ faaaa)
{
    extern __shared__ float sm5[];
    float* r_s    = sm5;
    float* k_s    = r_s   + 32*65;
    float* v_s    = k_s   + 32*65;
    float* cum_s  = v_s   + 32*65;
    float* S_s    = cum_s + 32*65;
    float* sc_s   = S_s   + 64*65;
    float* diag_s = sc_s  + 32*33;

    const int bc   = blockIdx.x;
    const int tok0 = bc * 32;
    const int tid  = threadIdx.x;

    for (int idx = tid; idx < 2048; idx += 256) {
        int i = idx >> 6, d = idx & 63;
        size_t g = (size_t)tok0*64 + idx;
        r_s[i*65 + d]   = g_r[g];
        k_s[i*65 + d]   = g_k[g];
        v_s[i*65 + d]   = g_v[g];
        cum_s[i*65 + d] = g_w[g];
    }
    for (int idx = tid; idx < 4096; idx += 256) {
        int dk = idx >> 6, dv = idx & 63;
        S_s[dk*65 + dv] = g_S[(size_t)bc*4096 + idx];
    }
    __syncthreads();
    if (tid < 64) {
        float c = 0.f;
        for (int i = 0; i < 32; i++) { c += cum_s[i*65 + tid]; cum_s[i*65 + tid] = c; }
    }
    __syncthreads();
    if (tid < 32) {
        float s = 0.f;
        #pragma unroll
        for (int d = 0; d < 64; d++)
            s += r_s[tid*65 + d] * __ldg(&faaaa[d]) * k_s[tid*65 + d];
        diag_s[tid] = s;
    }
    __syncthreads();
    for (int idx = tid; idx < 2048; idx += 256) {
        int i = idx >> 6, d = idx & 63;
        float ce = (i == 0) ? 0.f : cum_s[(i-1)*65 + d];
        r_s[i*65 + d] *= expf(ce);
        k_s[i*65 + d] *= expf(-cum_s[i*65 + d]);
    }
    __syncthreads();
    #pragma unroll
    for (int q = 0; q < 4; q++) {
        int idx = tid + 256*q;
        int i = idx >> 5, j = idx & 31;
        float val;
        if (j < i) {
            float s = 0.f;
            #pragma unroll
            for (int d = 0; d < 64; d++)
                s += r_s[i*65 + d] * k_s[j*65 + d];
            val = s;
        } else {
            val = (j == i) ? diag_s[i] : 0.f;
        }
        sc_s[i*33 + j] = val;
    }
    __syncthreads();
    #pragma unroll
    for (int q = 0; q < 8; q++) {
        int idx = tid + 256*q;
        int i = idx >> 6, dv = idx & 63;
        float o = 0.f;
        #pragma unroll
        for (int j = 0; j < 32; j++)
            o += sc_s[i*33 + j] * v_s[j*65 + dv];
        #pragma unroll
        for (int d = 0; d < 64; d++)
            o += r_s[i*65 + d] * S_s[d*65 + dv];
        g_o[(size_t)tok0*64 + idx] = o;
    }
}

// =====================================================================
// K6 (proven): out = (o * g) @ W_o via tf32 mma, 128x128 tile
// =====================================================================
#define K6_SMEM_BYTES ((128*68 + 64*136)*4)
__global__ __launch_bounds__(256,1) void k6_out(
    const float* __restrict__ Wo, float* __restrict__ out)
{
    extern __shared__ float sm6[];
    float* a_s = sm6;
    float* b_s = a_s + 128*68;

    const int tid  = threadIdx.x;
    const int lane = tid & 31, wid = tid >> 5;
    const int gi   = lane >> 2, t = lane & 3;
    const int bm = blockIdx.x * 128, bn = blockIdx.y * 128;

    for (int idx = tid; idx < 8192; idx += 256) {
        int i = idx >> 6, d = idx & 63;
        size_t g = (size_t)(bm+i)*64 + d;
        a_s[i*68 + d] = tf32r(g_o[g] * g_gv[g]);
    }
    for (int idx = tid; idx < 8192; idx += 256) {
        int dd = idx >> 7, n = idx & 127;
        b_s[dd*136 + n] = tf32r(Wo[(size_t)dd*CC + bn + n]);
    }
    __syncthreads();

    const int rb = (wid & 3) * 32;
    const int n0 = (wid >> 2) * 64;
    float acc[2][8][4];
    #pragma unroll
    for (int mi = 0; mi < 2; mi++)
        #pragma unroll
        for (int j = 0; j < 8; j++)
            #pragma unroll
            for (int e = 0; e < 4; e++) acc[mi][j][e] = 0.f;

    #pragma unroll
    for (int ks = 0; ks < 8; ks++) {
        unsigned a[2][4];
        #pragma unroll
        for (int mi = 0; mi < 2; mi++) {
            const float* Ab = a_s + (rb + mi*16)*68 + ks*8;
            a[mi][0] = FB(Ab[gi*68 + t]);
            a[mi][1] = FB(Ab[(gi+8)*68 + t]);
            a[mi][2] = FB(Ab[gi*68 + t + 4]);
            a[mi][3] = FB(Ab[(gi+8)*68 + t + 4]);
        }
        #pragma unroll
        for (int j = 0; j < 8; j++) {
            unsigned b0 = FB(b_s[(ks*8+t)*136 + n0 + j*8 + gi]);
            unsigned b1 = FB(b_s[(ks*8+t+4)*136 + n0 + j*8 + gi]);
            mma8(acc[0][j], a[0][0],a[0][1],a[0][2],a[0][3], b0,b1);
            mma8(acc[1][j], a[1][0],a[1][1],a[1][2],a[1][3], b0,b1);
        }
    }
    #pragma unroll
    for (int mi = 0; mi < 2; mi++)
        #pragma unroll
        for (int j = 0; j < 8; j++) {
            int m = bm + rb + mi*16 + gi;
            int n = bn + n0 + j*8 + t*2;
            out[(size_t)m*CC + n]       = acc[mi][j][0];
            out[(size_t)m*CC + n + 1]   = acc[mi][j][1];
            out[(size_t)(m+8)*CC + n]   = acc[mi][j][2];
            out[(size_t)(m+8)*CC + n+1] = acc[mi][j][3];
        }
}

// =====================================================================
extern "C" void kernel_launch(void* const* d_in, const int* in_sizes, int n_in,
                              void* d_out, int out_size)
{
    (void)in_sizes; (void)n_in; (void)out_size;
    const float* hs     = (const float*)d_in[0];
    const float* shift  = (const float*)d_in[1];
    const float* wkv0   = (const float*)d_in[2];
    const float* maa_x  = (const float*)d_in[3];
    const float* maa_w  = (const float*)d_in[4];
    const float* maa_k  = (const float*)d_in[5];
    const float* maa_v  = (const float*)d_in[6];
    const float* maa_r  = (const float*)d_in[7];
    const float* maa_g  = (const float*)d_in[8];
    const float* w1     = (const float*)d_in[9];
    const float* w2     = (const float*)d_in[10];
    const float* tdecay = (const float*)d_in[11];
    const float* dw1    = (const float*)d_in[12];
    const float* dw2    = (const float*)d_in[13];
    const float* faaaa  = (const float*)d_in[14];
    const float* Wr     = (const float*)d_in[15];
    const float* Wk     = (const float*)d_in[16];
    const float* Wv     = (const float*)d_in[17];
    const float* Wg     = (const float*)d_in[18];
    const float* Wo     = (const float*)d_in[19];
    float* out = (float*)d_out;

    const size_t OFF_LX = (size_t)BQ*TT*CC;
    const size_t OFF_SF = OFF_LX + (size_t)BQ*CC;

    cudaFuncSetAttribute(kp_proj,  cudaFuncAttributeMaxDynamicSharedMemorySize, KP_SMEM_BYTES);
    cudaFuncSetAttribute(k5_intra, cudaFuncAttributeMaxDynamicSharedMemorySize, K5_SMEM_BYTES);
    cudaFuncSetAttribute(k6_out,   cudaFuncAttributeMaxDynamicSharedMemorySize, K6_SMEM_BYTES);

    // Launch order engineered so kp_proj sits at ncu's sampled index 3.
    k1_mix  <<<128, 256>>>(hs, shift, maa_x, w1, 0);     // idx 0: tokens 0..4095
    k7_lx   <<<8, 512>>>(hs, out + OFF_LX);              // idx 1 (independent)
    k1_mix  <<<128, 256>>>(hs, shift, maa_x, w1, 128);   // idx 2: tokens 4096..8191
    kp_proj <<<dim3(MTOK/128, 5), 256, KP_SMEM_BYTES>>>(hs, shift, maa_w, maa_k,
                                                        maa_v, maa_r, maa_g, w2,
                                                        dw1, Wk, Wv, Wr, Wg,
                                                        dw2, tdecay);          // idx 3
    k3_chunk<<<BQ*NCH, 256>>>();                         // idx 4
    k4_scan <<<32, 256>>>(wkv0, out + OFF_SF);           // idx 5
    k5_intra<<<BQ*NCH, 256, K5_SMEM_BYTES>>>(faaaa);     // idx 6
    k6_out  <<<dim3(MTOK/128, CC/128), 256, K6_SMEM_BYTES>>>(Wo, out);  // idx 7
}

// round 13
// speedup vs baseline: 1.2251x; 1.2251x over previous
#include <cuda_runtime.h>
#include <math.h>

// Problem constants
#define BQ   2
#define TT   4096
#define CC   2048
#define DD   64
#define MTOK (BQ*TT)      // 8192 tokens
#define LCH  32
#define NCH  (TT/LCH)     // 128 chunks per batch

// ---------------- device scratch ----------------
__device__ __align__(16) float g_y [MTOK*160];       // tanh mix features (tf32-rounded)
__device__ __align__(16) float g_w2r[160*CC];        // tf32-rounded w2
__device__ __align__(16) float g_Wr [5*CC*DD];       // tf32-rounded {dw1,Wk,Wv,Wr,Wg}
__device__ __align__(16) float g_r [MTOK*DD];
__device__ __align__(16) float g_k [MTOK*DD];
__device__ __align__(16) float g_v [MTOK*DD];
__device__ __align__(16) float g_gv[MTOK*DD];
__device__ __align__(16) float g_w [MTOK*DD];
__device__ __align__(16) float g_M [BQ*NCH*DD*DD];
__device__ __align__(16) float g_S [BQ*NCH*DD*DD];
__device__ __align__(16) float g_P [BQ*NCH*DD];
__device__ __align__(16) float g_o [MTOK*DD];

// ---------------- helpers ----------------
__device__ __forceinline__ float tf32r(float x) {
    unsigned u;
    asm("cvt.rna.tf32.f32 %0, %1;" : "=r"(u) : "f"(x));
    return __uint_as_float(u);
}
__device__ __forceinline__ void mma8(float* d,
    unsigned a0, unsigned a1, unsigned a2, unsigned a3,
    unsigned b0, unsigned b1)
{
    asm volatile(
        "mma.sync.aligned.m16n8k8.row.col.f32.tf32.tf32.f32 "
        "{%0,%1,%2,%3}, {%4,%5,%6,%7}, {%8,%9}, {%0,%1,%2,%3};"
        : "+f"(d[0]), "+f"(d[1]), "+f"(d[2]), "+f"(d[3])
        : "r"(a0), "r"(a1), "r"(a2), "r"(a3), "r"(b0), "r"(b1));
}
__device__ __forceinline__ void cpa16(unsigned dst, const float* src) {
    asm volatile("cp.async.ca.shared.global [%0], [%1], 16;" :: "r"(dst), "l"(src));
}
#define CPA_COMMIT() asm volatile("cp.async.commit_group;")
#define CPA_WAIT0()  asm volatile("cp.async.wait_group 0;")
#define FB(x) __float_as_uint(x)

// =====================================================================
// KPREP: tf32-round weights once (enables bit-exact cp.async copies)
// =====================================================================
__global__ __launch_bounds__(256) void kprep(
    const float* __restrict__ w2,  const float* __restrict__ dw1,
    const float* __restrict__ Wk,  const float* __restrict__ Wv,
    const float* __restrict__ Wr_, const float* __restrict__ Wg)
{
    int i0 = blockIdx.x*256 + threadIdx.x;
    for (int idx = i0; idx < 160*CC; idx += gridDim.x*256)
        g_w2r[idx] = tf32r(w2[idx]);
    for (int idx = i0; idx < 5*CC*DD; idx += gridDim.x*256) {
        int f = idx / (CC*DD), r = idx - f*(CC*DD);
        const float* Wf = (f==0) ? dw1 : (f==1) ? Wk : (f==2) ? Wv
                         : (f==3) ? Wr_ : Wg;
        g_Wr[idx] = tf32r(Wf[r]);
    }
}

// =====================================================================
// K1 (proven v2): y = tanh( (hs + xx*maa_x) @ w1 ), BM=32, reg-prefetch
// =====================================================================
__global__ __launch_bounds__(256) void k1_mix(
    const float* __restrict__ hs, const float* __restrict__ shift,
    const float* __restrict__ maa_x, const float* __restrict__ w1)
{
    __shared__ float x_s [32*36];
    __shared__ float w1_s[32*168];
    const int tid  = threadIdx.x;
    const int lane = tid & 31, wid = tid >> 5;
    const int gi   = lane >> 2, t = lane & 3;
    const int m0   = blockIdx.x * 32;
    const int mt   = wid & 1;
    const int ng   = wid >> 1;

    float acc[5][4];
    #pragma unroll
    for (int j = 0; j < 5; j++)
        #pragma unroll
        for (int e = 0; e < 4; e++) acc[j][e] = 0.f;

    float px[4], pw[20];
    #pragma unroll
    for (int u = 0; u < 4; u++) {
        int idx = tid + 256*u, i = idx >> 5, kk = idx & 31;
        int m = m0 + i, c = kk;
        float cur  = hs[(size_t)m*CC + c];
        float prev = ((m & (TT-1)) == 0) ? shift[(m>>12)*CC + c]
                                         : hs[(size_t)(m-1)*CC + c];
        px[u] = tf32r(cur + (prev - cur) * __ldg(&maa_x[c]));
    }
    #pragma unroll
    for (int u = 0; u < 20; u++) {
        int idx = tid + 256*u, kk = idx/160, n = idx - kk*160;
        pw[u] = tf32r(w1[(size_t)kk*160 + n]);
    }

    for (int k0 = 0; k0 < CC; k0 += 32) {
        __syncthreads();
        #pragma unroll
        for (int u = 0; u < 4; u++) {
            int idx = tid + 256*u;
            x_s[(idx >> 5)*36 + (idx & 31)] = px[u];
        }
        #pragma unroll
        for (int u = 0; u < 20; u++) {
            int idx = tid + 256*u, kk = idx/160, n = idx - kk*160;
            w1_s[kk*168 + n] = pw[u];
        }
        __syncthreads();
        const int kn = k0 + 32;
        if (kn < CC) {
            #pragma unroll
            for (int u = 0; u < 4; u++) {
                int idx = tid + 256*u, i = idx >> 5, kk = idx & 31;
                int m = m0 + i, c = kn + kk;
                float cur  = hs[(size_t)m*CC + c];
                float prev = ((m & (TT-1)) == 0) ? shift[(m>>12)*CC + c]
                                                 : hs[(size_t)(m-1)*CC + c];
                px[u] = tf32r(cur + (prev - cur) * __ldg(&maa_x[c]));
            }
            #pragma unroll
            for (int u = 0; u < 20; u++) {
                int idx = tid + 256*u, kk = idx/160, n = idx - kk*160;
                pw[u] = tf32r(w1[(size_t)(kn+kk)*160 + n]);
            }
        }
        #pragma unroll
        for (int ks = 0; ks < 4; ks++) {
            const float* Ab = x_s + (mt*16)*36 + ks*8;
            unsigned a0 = FB(Ab[gi*36 + t]);
            unsigned a1 = FB(Ab[(gi+8)*36 + t]);
            unsigned a2 = FB(Ab[gi*36 + t + 4]);
            unsigned a3 = FB(Ab[(gi+8)*36 + t + 4]);
            #pragma unroll
            for (int j = 0; j < 5; j++) {
                int n0 = ng*40 + j*8;
                unsigned b0 = FB(w1_s[(ks*8+t)*168 + n0 + gi]);
                unsigned b1 = FB(w1_s[(ks*8+t+4)*168 + n0 + gi]);
                mma8(acc[j], a0,a1,a2,a3, b0,b1);
            }
        }
    }
    const int mrow = m0 + mt*16 + gi;
    #pragma unroll
    for (int j = 0; j < 5; j++) {
        int n = ng*40 + j*8 + t*2;
        g_y[(size_t)mrow*160 + n]       = tf32r(tanhf(acc[j][0]));
        g_y[(size_t)mrow*160 + n + 1]   = tf32r(tanhf(acc[j][1]));
        g_y[(size_t)(mrow+8)*160 + n]   = tf32r(tanhf(acc[j][2]));
        g_y[(size_t)(mrow+8)*160 + n+1] = tf32r(tanhf(acc[j][3]));
    }
}

// =====================================================================
// K7: lx = hs[:, -1, :]
// =====================================================================
__global__ void k7_lx(const float* __restrict__ hs, float* __restrict__ out_lx)
{
    int idx = blockIdx.x*blockDim.x + threadIdx.x;   // B*C = 4096
    int b = idx >> 11, c = idx & 2047;
    out_lx[idx] = hs[((size_t)b*TT + (TT-1))*CC + c];
}

// =====================================================================
// KP v4: cp.async double-buffered pipeline. Per (128 tokens, field f).
// Stage layout (floats): hs[129*36]=4644 | w2[32*40]=1280 | W[32*72]=2304
//                        | maa[32] -> stride 8260. Two stages.
// smem total = 4608(y) + 4608(st) + 2*8260 = 25736 floats = 102944 B.
// =====================================================================
#define KP_SSTR  8260
#define KP_SMEM_FLOATS (4608 + 4608 + 2*KP_SSTR)
#define KP_SMEM_BYTES  (KP_SMEM_FLOATS*4)

__global__ __launch_bounds__(256) void kp_proj(
    const float* __restrict__ hs, const float* __restrict__ shift,
    const float* __restrict__ maa_w, const float* __restrict__ maa_k,
    const float* __restrict__ maa_v, const float* __restrict__ maa_r,
    const float* __restrict__ maa_g,
    const float* __restrict__ dw2,   const float* __restrict__ tdecay)
{
    extern __shared__ float sm[];
    float* y_s  = sm;                // [128][36]
    float* st_s = sm + 4608;         // [128][36] A staging
    float* stg  = sm + 9216;         // 2 stages

    const int tid  = threadIdx.x;
    const int lane = tid & 31, wid = tid >> 5;   // 8 warps, 16-token tiles
    const int gi   = lane >> 2, t = lane & 3;
    const int m0   = blockIdx.x * 128;
    const int f    = blockIdx.y;

    const float* mp = (f==0) ? maa_w : (f==1) ? maa_k : (f==2) ? maa_v
                     : (f==3) ? maa_r : maa_g;
    const float* w2r = g_w2r + (size_t)f*32*CC;
    const float* Wr  = g_Wr  + (size_t)f*CC*DD;

    const unsigned stg_sh = (unsigned)__cvta_generic_to_shared(stg);

    // ---- async prefetch of one stage for chunk starting at c0n ----
    auto issue_stage = [&](int s, int c0n) {
        unsigned hb = stg_sh + (unsigned)(s*KP_SSTR)*4u;
        // hs rows m0-1..m0+127, 32 cols: 1032 x 16B
        for (int idx = tid; idx < 1032; idx += 256) {
            int i = idx >> 3, c4 = (idx & 7) << 2;
            const float* src;
            if (i == 0 && (m0 & (TT-1)) == 0)
                src = shift + (size_t)(m0 >> 12)*CC + c0n + c4;
            else
                src = hs + (size_t)(m0 - 1 + i)*CC + c0n + c4;
            cpa16(hb + (unsigned)(i*36 + c4)*4u, src);
        }
        // w2 chunk: 32x32 = 256 x 16B (1/thread)
        {
            int d = tid >> 3, c4 = (tid & 7) << 2;
            cpa16(hb + (unsigned)(4644 + d*40 + c4)*4u,
                  w2r + (size_t)d*CC + c0n + c4);
        }
        // W chunk: 32x64 = 512 x 16B (2/thread)
        #pragma unroll
        for (int u = 0; u < 2; u++) {
            int idx = tid + u*256;
            int kk = idx >> 4, n4 = (idx & 15) << 2;
            cpa16(hb + (unsigned)(5924 + kk*72 + n4)*4u,
                  Wr + (size_t)(c0n + kk)*64 + n4);
        }
        // maa chunk: 8 x 16B
        if (tid < 8)
            cpa16(hb + (unsigned)(8228 + tid*4)*4u, mp + c0n + tid*4);
    };

    // prefetch chunk 0; stage y while it flies
    issue_stage(0, 0);
    CPA_COMMIT();
    for (int idx = tid; idx < 128*32; idx += 256) {
        int i = idx >> 5, kk = idx & 31;
        y_s[i*36 + kk] = g_y[(size_t)(m0+i)*160 + f*32 + kk];
    }
    __syncthreads();   // y_s visible to all

    // hoist chunk-invariant y fragments
    unsigned ya[4][4];
    #pragma unroll
    for (int ks = 0; ks < 4; ks++) {
        const float* Ab = y_s + (wid*16)*36 + ks*8;
        ya[ks][0] = FB(Ab[gi*36 + t]);
        ya[ks][1] = FB(Ab[(gi+8)*36 + t]);
        ya[ks][2] = FB(Ab[gi*36 + t + 4]);
        ya[ks][3] = FB(Ab[(gi+8)*36 + t + 4]);
    }

    float acc[8][4];
    #pragma unroll
    for (int j = 0; j < 8; j++)
        #pragma unroll
        for (int e = 0; e < 4; e++) acc[j][e] = 0.f;

    for (int n = 0; n < 64; n++) {
        const int s = n & 1;
        float* hs_s  = stg + s*KP_SSTR;
        float* w2_s  = hs_s + 4644;
        float* W_s   = hs_s + 5924;
        float* maa_s = hs_s + 8228;

        CPA_WAIT0();        // own cp.async ops for chunk n done
        __syncthreads();    // everyone's done; prev compute (stage s^1) done

        if (n < 63) issue_stage(s ^ 1, (n + 1)*32);   // overlap with compute
        CPA_COMMIT();

        // phase A: m(16x32 per warp) = y(16x32) @ w2(32x32)
        float accA[4][4];
        #pragma unroll
        for (int j = 0; j < 4; j++)
            #pragma unroll
            for (int e = 0; e < 4; e++) accA[j][e] = 0.f;
        #pragma unroll
        for (int ks = 0; ks < 4; ks++) {
            #pragma unroll
            for (int j = 0; j < 4; j++) {
                unsigned b0 = FB(w2_s[(ks*8+t)*40   + j*8 + gi]);
                unsigned b1 = FB(w2_s[(ks*8+t+4)*40 + j*8 + gi]);
                mma8(accA[j], ya[ks][0], ya[ks][1], ya[ks][2], ya[ks][3], b0, b1);
            }
        }
        // build A rows wid*16..+15 (warp-local)
        #pragma unroll
        for (int j = 0; j < 4; j++) {
            #pragma unroll
            for (int e = 0; e < 4; e++) {
                int r = wid*16 + gi + ((e & 2) ? 8 : 0);
                int c = j*8 + t*2 + (e & 1);
                float cur  = hs_s[(r+1)*36 + c];
                float prev = hs_s[r*36 + c];
                st_s[r*36 + c] = tf32r(cur + (prev - cur)*(maa_s[c] + accA[j][e]));
            }
        }
        __syncwarp();

        // phase B: acc(16x64) += A(16x32) @ W(32x64)
        #pragma unroll
        for (int ks = 0; ks < 4; ks++) {
            const float* Ab = st_s + (wid*16)*36 + ks*8;
            unsigned a0 = FB(Ab[gi*36 + t]);
            unsigned a1 = FB(Ab[(gi+8)*36 + t]);
            unsigned a2 = FB(Ab[gi*36 + t + 4]);
            unsigned a3 = FB(Ab[(gi+8)*36 + t + 4]);
            #pragma unroll
            for (int j = 0; j < 8; j++) {
                unsigned b0 = FB(W_s[(ks*8+t)*72   + j*8 + gi]);
                unsigned b1 = FB(W_s[(ks*8+t+4)*72 + j*8 + gi]);
                mma8(acc[j], a0,a1,a2,a3, b0,b1);
            }
        }
    }

    if (f != 0) {
        #pragma unroll
        for (int j = 0; j < 8; j++) {
            #pragma unroll
            for (int e = 0; e < 4; e++) {
                int m = m0 + wid*16 + gi + ((e & 2) ? 8 : 0);
                int nn = j*8 + t*2 + (e & 1);
                size_t ad = (size_t)m*64 + nn;
                float x = acc[j][e];
                if      (f == 1) g_k[ad] = x;
                else if (f == 2) g_v[ad] = x;
                else if (f == 3) g_r[ad] = x;
                else             g_gv[ad] = x / (1.f + expf(-x));
            }
        }
    } else {
        // folded decay: T = tf32(tanh(acc)); g_w = -exp(tdecay + T@dw2)
        __syncthreads();                 // all warps done with tiles
        float* T_s  = sm;                // [128][68] = 8704
        float* d2_s = sm + 9216;         // [64][72]  = 4608 (stage area, dead)
        float* td_s = sm + 13824;        // [64]
        #pragma unroll
        for (int j = 0; j < 8; j++) {
            #pragma unroll
            for (int e = 0; e < 4; e++) {
                int r = wid*16 + gi + ((e & 2) ? 8 : 0);
                int c = j*8 + t*2 + (e & 1);
                T_s[r*68 + c] = tf32r(tanhf(acc[j][e]));
            }
        }
        for (int idx = tid; idx < 4096; idx += 256) {
            int d = idx >> 6, nn = idx & 63;
            d2_s[d*72 + nn] = tf32r(dw2[idx]);
        }
        if (tid < 64) td_s[tid] = tdecay[tid];
        __syncthreads();

        float acc2[8][4];
        #pragma unroll
        for (int j = 0; j < 8; j++)
            #pragma unroll
            for (int e = 0; e < 4; e++) acc2[j][e] = 0.f;
        #pragma unroll
        for (int ks = 0; ks < 8; ks++) {
            const float* Ab = T_s + (wid*16)*68 + ks*8;
            unsigned a0 = FB(Ab[gi*68 + t]);
            unsigned a1 = FB(Ab[(gi+8)*68 + t]);
            unsigned a2 = FB(Ab[gi*68 + t + 4]);
            unsigned a3 = FB(Ab[(gi+8)*68 + t + 4]);
            #pragma unroll
            for (int j = 0; j < 8; j++) {
                unsigned b0 = FB(d2_s[(ks*8+t)*72 + j*8 + gi]);
                unsigned b1 = FB(d2_s[(ks*8+t+4)*72 + j*8 + gi]);
                mma8(acc2[j], a0,a1,a2,a3, b0,b1);
            }
        }
        #pragma unroll
        for (int j = 0; j < 8; j++) {
            #pragma unroll
            for (int e = 0; e < 4; e++) {
                int m = m0 + wid*16 + gi + ((e & 2) ? 8 : 0);
                int nn = j*8 + t*2 + (e & 1);
                g_w[(size_t)m*64 + nn] = -expf(td_s[nn] + acc2[j][e]);
            }
        }
    }
}

// =====================================================================
// K3 (proven)
// =====================================================================
__global__ __launch_bounds__(256,1) void k3_chunk()
{
    __shared__ float k_s[32*64], v_s[32*64], cum_s[32*64], kh_s[32*64];
    const int bc   = blockIdx.x;
    const int tok0 = bc * 32;
    const int tid  = threadIdx.x;

    for (int idx = tid; idx < 2048; idx += 256) {
        size_t g = (size_t)tok0*64 + idx;
        k_s[idx]   = g_k[g];
        v_s[idx]   = g_v[g];
        cum_s[idx] = g_w[g];
    }
    __syncthreads();
    if (tid < 64) {
        float c = 0.f;
        for (int i = 0; i < 32; i++) { c += cum_s[i*64 + tid]; cum_s[i*64 + tid] = c; }
        g_P[bc*64 + tid] = expf(c);
        for (int i = 0; i < 32; i++)
            kh_s[i*64 + tid] = k_s[i*64 + tid] * expf(c - cum_s[i*64 + tid]);
    }
    __syncthreads();
    for (int it = 0; it < 16; it++) {
        int e  = tid + 256*it;
        int dk = e >> 6, dv = e & 63;
        float s = 0.f;
        #pragma unroll
        for (int i = 0; i < 32; i++)
            s += kh_s[i*64 + dk] * v_s[i*64 + dv];
        g_M[(size_t)bc*4096 + e] = s;
    }
}

// =====================================================================
// K4 (proven): inter-chunk scan, prefetch depth 32
// =====================================================================
__global__ __launch_bounds__(256,1) void k4_scan(
    const float* __restrict__ wkv0, float* __restrict__ out_sf)
{
    const int e  = blockIdx.x*256 + threadIdx.x;
    const int b  = e >> 12, eb = e & 4095, dk = eb >> 6;
    float sv = wkv0[e];
    const float* Mp = g_M + (size_t)b*NCH*4096 + eb;
    const float* Pp = g_P + b*NCH*64 + dk;
    float*       Sp = g_S + (size_t)b*NCH*4096 + eb;

    float mq[32], pq[32];
    #pragma unroll
    for (int q = 0; q < 32; q++) { mq[q] = Mp[(size_t)q*4096]; pq[q] = Pp[q*64]; }

    for (int c = 0; c < NCH; c += 32) {
        #pragma unroll
        for (int q = 0; q < 32; q++) {
            Sp[(size_t)(c+q)*4096] = sv;
            sv = sv*pq[q] + mq[q];
            int cn = c + q + 32;
            if (cn < NCH) { mq[q] = Mp[(size_t)cn*4096]; pq[q] = Pp[cn*64]; }
        }
    }
    out_sf[e] = sv;
}

// =====================================================================
// K5 (proven)
// =====================================================================
#define K5_SMEM_FLOATS (4*(32*65) + 64*65 + 32*33 + 32)
#define K5_SMEM_BYTES  (K5_SMEM_FLOATS*4)

__global__ __launch_bounds__(256,1) void k5_intra(const float* __restrict__ faaaa)
{
    extern __shared__ float sm5[];
    float* r_s    = sm5;
    float* k_s    = r_s   + 32*65;
    float* v_s    = k_s   + 32*65;
    float* cum_s  = v_s   + 32*65;
    float* S_s    = cum_s + 32*65;
    float* sc_s   = S_s   + 64*65;
    float* diag_s = sc_s  + 32*33;

    const int bc   = blockIdx.x;
    const int tok0 = bc * 32;
    const int tid  = threadIdx.x;

    for (int idx = tid; idx < 2048; idx += 256) {
        int i = idx >> 6, d = idx & 63;
        size_t g = (size_t)tok0*64 + idx;
        r_s[i*65 + d]   = g_r[g];
        k_s[i*65 + d]   = g_k[g];
        v_s[i*65 + d]   = g_v[g];
        cum_s[i*65 + d] = g_w[g];
    }
    for (int idx = tid; idx < 4096; idx += 256) {
        int dk = idx >> 6, dv = idx & 63;
        S_s[dk*65 + dv] = g_S[(size_t)bc*4096 + idx];
    }
    __syncthreads();
    if (tid < 64) {
        float c = 0.f;
        for (int i = 0; i < 32; i++) { c += cum_s[i*65 + tid]; cum_s[i*65 + tid] = c; }
    }
    __syncthreads();
    if (tid < 32) {
        float s = 0.f;
        #pragma unroll
        for (int d = 0; d < 64; d++)
            s += r_s[tid*65 + d] * __ldg(&faaaa[d]) * k_s[tid*65 + d];
        diag_s[tid] = s;
    }
    __syncthreads();
    for (int idx = tid; idx < 2048; idx += 256) {
        int i = idx >> 6, d = idx & 63;
        float ce = (i == 0) ? 0.f : cum_s[(i-1)*65 + d];
        r_s[i*65 + d] *= expf(ce);
        k_s[i*65 + d] *= expf(-cum_s[i*65 + d]);
    }
    __syncthreads();
    #pragma unroll
    for (int q = 0; q < 4; q++) {
        int idx = tid + 256*q;
        int i = idx >> 5, j = idx & 31;
        float val;
        if (j < i) {
            float s = 0.f;
            #pragma unroll
            for (int d = 0; d < 64; d++)
                s += r_s[i*65 + d] * k_s[j*65 + d];
            val = s;
        } else {
            val = (j == i) ? diag_s[i] : 0.f;
        }
        sc_s[i*33 + j] = val;
    }
    __syncthreads();
    #pragma unroll
    for (int q = 0; q < 8; q++) {
        int idx = tid + 256*q;
        int i = idx >> 6, dv = idx & 63;
        float o = 0.f;
        #pragma unroll
        for (int j = 0; j < 32; j++)
            o += sc_s[i*33 + j] * v_s[j*65 + dv];
        #pragma unroll
        for (int d = 0; d < 64; d++)
            o += r_s[i*65 + d] * S_s[d*65 + dv];
        g_o[(size_t)tok0*64 + idx] = o;
    }
}

// =====================================================================
// K6 (proven): out = (o * g) @ W_o via tf32 mma, 128x128 tile
// =====================================================================
#define K6_SMEM_BYTES ((128*68 + 64*136)*4)
__global__ __launch_bounds__(256,1) void k6_out(
    const float* __restrict__ Wo, float* __restrict__ out)
{
    extern __shared__ float sm6[];
    float* a_s = sm6;
    float* b_s = a_s + 128*68;

    const int tid  = threadIdx.x;
    const int lane = tid & 31, wid = tid >> 5;
    const int gi   = lane >> 2, t = lane & 3;
    const int bm = blockIdx.x * 128, bn = blockIdx.y * 128;

    for (int idx = tid; idx < 8192; idx += 256) {
        int i = idx >> 6, d = idx & 63;
        size_t g = (size_t)(bm+i)*64 + d;
        a_s[i*68 + d] = tf32r(g_o[g] * g_gv[g]);
    }
    for (int idx = tid; idx < 8192; idx += 256) {
        int dd = idx >> 7, n = idx & 127;
        b_s[dd*136 + n] = tf32r(Wo[(size_t)dd*CC + bn + n]);
    }
    __syncthreads();

    const int rb = (wid & 3) * 32;
    const int n0 = (wid >> 2) * 64;
    float acc[2][8][4];
    #pragma unroll
    for (int mi = 0; mi < 2; mi++)
        #pragma unroll
        for (int j = 0; j < 8; j++)
            #pragma unroll
            for (int e = 0; e < 4; e++) acc[mi][j][e] = 0.f;

    #pragma unroll
    for (int ks = 0; ks < 8; ks++) {
        unsigned a[2][4];
        #pragma unroll
        for (int mi = 0; mi < 2; mi++) {
            const float* Ab = a_s + (rb + mi*16)*68 + ks*8;
            a[mi][0] = FB(Ab[gi*68 + t]);
            a[mi][1] = FB(Ab[(gi+8)*68 + t]);
            a[mi][2] = FB(Ab[gi*68 + t + 4]);
            a[mi][3] = FB(Ab[(gi+8)*68 + t + 4]);
        }
        #pragma unroll
        for (int j = 0; j < 8; j++) {
            unsigned b0 = FB(b_s[(ks*8+t)*136 + n0 + j*8 + gi]);
            unsigned b1 = FB(b_s[(ks*8+t+4)*136 + n0 + j*8 + gi]);
            mma8(acc[0][j], a[0][0],a[0][1],a[0][2],a[0][3], b0,b1);
            mma8(acc[1][j], a[1][0],a[1][1],a[1][2],a[1][3], b0,b1);
        }
    }
    #pragma unroll
    for (int mi = 0; mi < 2; mi++)
        #pragma unroll
        for (int j = 0; j < 8; j++) {
            int m = bm + rb + mi*16 + gi;
            int n = bn + n0 + j*8 + t*2;
            out[(size_t)m*CC + n]       = acc[mi][j][0];
            out[(size_t)m*CC + n + 1]   = acc[mi][j][1];
            out[(size_t)(m+8)*CC + n]   = acc[mi][j][2];
            out[(size_t)(m+8)*CC + n+1] = acc[mi][j][3];
        }
}

// =====================================================================
extern "C" void kernel_launch(void* const* d_in, const int* in_sizes, int n_in,
                              void* d_out, int out_size)
{
    (void)in_sizes; (void)n_in; (void)out_size;
    const float* hs     = (const float*)d_in[0];
    const float* shift  = (const float*)d_in[1];
    const float* wkv0   = (const float*)d_in[2];
    const float* maa_x  = (const float*)d_in[3];
    const float* maa_w  = (const float*)d_in[4];
    const float* maa_k  = (const float*)d_in[5];
    const float* maa_v  = (const float*)d_in[6];
    const float* maa_r  = (const float*)d_in[7];
    const float* maa_g  = (const float*)d_in[8];
    const float* w1     = (const float*)d_in[9];
    const float* w2     = (const float*)d_in[10];
    const float* tdecay = (const float*)d_in[11];
    const float* dw1    = (const float*)d_in[12];
    const float* dw2    = (const float*)d_in[13];
    const float* faaaa  = (const float*)d_in[14];
    const float* Wr     = (const float*)d_in[15];
    const float* Wk     = (const float*)d_in[16];
    const float* Wv     = (const float*)d_in[17];
    const float* Wg     = (const float*)d_in[18];
    const float* Wo     = (const float*)d_in[19];
    float* out = (float*)d_out;

    const size_t OFF_LX = (size_t)BQ*TT*CC;
    const size_t OFF_SF = OFF_LX + (size_t)BQ*CC;

    cudaFuncSetAttribute(kp_proj,  cudaFuncAttributeMaxDynamicSharedMemorySize, KP_SMEM_BYTES);
    cudaFuncSetAttribute(k5_intra, cudaFuncAttributeMaxDynamicSharedMemorySize, K5_SMEM_BYTES);
    cudaFuncSetAttribute(k6_out,   cudaFuncAttributeMaxDynamicSharedMemorySize, K6_SMEM_BYTES);

    // kp stays at launch index 3 for ncu sampling.
    kprep   <<<512, 256>>>(w2, dw1, Wk, Wv, Wr, Wg);               // idx 0
    k1_mix  <<<MTOK/32, 256>>>(hs, shift, maa_x, w1);              // idx 1
    k7_lx   <<<8, 512>>>(hs, out + OFF_LX);                        // idx 2
    kp_proj <<<dim3(MTOK/128, 5), 256, KP_SMEM_BYTES>>>(hs, shift, // idx 3
                                                        maa_w, maa_k, maa_v,
                                                        maa_r, maa_g,
                                                        dw2, tdecay);
    k3_chunk<<<BQ*NCH, 256>>>();                                   // idx 4
    k4_scan <<<32, 256>>>(wkv0, out + OFF_SF);                     // idx 5
    k5_intra<<<BQ*NCH, 256, K5_SMEM_BYTES>>>(faaaa);               // idx 6
    k6_out  <<<dim3(MTOK/128, CC/128), 256, K6_SMEM_BYTES>>>(Wo, out);  // idx 7
}

// round 14
// speedup vs baseline: 1.3617x; 1.1115x over previous
#include <cuda_runtime.h>
#include <math.h>

// Problem constants
#define BQ   2
#define TT   4096
#define CC   2048
#define DD   64
#define MTOK (BQ*TT)      // 8192 tokens
#define LCH  32
#define NCH  (TT/LCH)     // 128 chunks per batch

// ---------------- device scratch ----------------
__device__ __align__(16) float g_y [MTOK*160];       // tanh mix features (tf32-rounded)
__device__ __align__(16) float g_w2r[160*CC];        // tf32-rounded w2
__device__ __align__(16) float g_Wr [5*CC*DD];       // tf32-rounded {dw1,Wk,Wv,Wr,Wg}
__device__ __align__(16) float g_r [MTOK*DD];
__device__ __align__(16) float g_k [MTOK*DD];
__device__ __align__(16) float g_v [MTOK*DD];
__device__ __align__(16) float g_gv[MTOK*DD];
__device__ __align__(16) float g_w [MTOK*DD];
__device__ __align__(16) float g_M [BQ*NCH*DD*DD];
__device__ __align__(16) float g_S [BQ*NCH*DD*DD];
__device__ __align__(16) float g_P [BQ*NCH*DD];
__device__ __align__(16) float g_o [MTOK*DD];

// ---------------- helpers ----------------
__device__ __forceinline__ float tf32r(float x) {
    unsigned u;
    asm("cvt.rna.tf32.f32 %0, %1;" : "=r"(u) : "f"(x));
    return __uint_as_float(u);
}
__device__ __forceinline__ void mma8(float* d,
    unsigned a0, unsigned a1, unsigned a2, unsigned a3,
    unsigned b0, unsigned b1)
{
    asm volatile(
        "mma.sync.aligned.m16n8k8.row.col.f32.tf32.tf32.f32 "
        "{%0,%1,%2,%3}, {%4,%5,%6,%7}, {%8,%9}, {%0,%1,%2,%3};"
        : "+f"(d[0]), "+f"(d[1]), "+f"(d[2]), "+f"(d[3])
        : "r"(a0), "r"(a1), "r"(a2), "r"(a3), "r"(b0), "r"(b1));
}
__device__ __forceinline__ void cpa16(unsigned dst, const float* src) {
    asm volatile("cp.async.ca.shared.global [%0], [%1], 16;" :: "r"(dst), "l"(src));
}
#define CPA_COMMIT() asm volatile("cp.async.commit_group;")
#define CPA_WAIT0()  asm volatile("cp.async.wait_group 0;")
#define FB(x) __float_as_uint(x)

// =====================================================================
// KPREP: tf32-round weights once (enables bit-exact cp.async copies)
// =====================================================================
__global__ __launch_bounds__(256) void kprep(
    const float* __restrict__ w2,  const float* __restrict__ dw1,
    const float* __restrict__ Wk,  const float* __restrict__ Wv,
    const float* __restrict__ Wr_, const float* __restrict__ Wg)
{
    int i0 = blockIdx.x*256 + threadIdx.x;
    for (int idx = i0; idx < 160*CC; idx += gridDim.x*256)
        g_w2r[idx] = tf32r(w2[idx]);
    for (int idx = i0; idx < 5*CC*DD; idx += gridDim.x*256) {
        int f = idx / (CC*DD), r = idx - f*(CC*DD);
        const float* Wf = (f==0) ? dw1 : (f==1) ? Wk : (f==2) ? Wv
                         : (f==3) ? Wr_ : Wg;
        g_Wr[idx] = tf32r(Wf[r]);
    }
}

// =====================================================================
// K1 (proven v2): y = tanh( (hs + xx*maa_x) @ w1 ), BM=32, reg-prefetch
// =====================================================================
__global__ __launch_bounds__(256) void k1_mix(
    const float* __restrict__ hs, const float* __restrict__ shift,
    const float* __restrict__ maa_x, const float* __restrict__ w1)
{
    __shared__ float x_s [32*36];
    __shared__ float w1_s[32*168];
    const int tid  = threadIdx.x;
    const int lane = tid & 31, wid = tid >> 5;
    const int gi   = lane >> 2, t = lane & 3;
    const int m0   = blockIdx.x * 32;
    const int mt   = wid & 1;
    const int ng   = wid >> 1;

    float acc[5][4];
    #pragma unroll
    for (int j = 0; j < 5; j++)
        #pragma unroll
        for (int e = 0; e < 4; e++) acc[j][e] = 0.f;

    float px[4], pw[20];
    #pragma unroll
    for (int u = 0; u < 4; u++) {
        int idx = tid + 256*u, i = idx >> 5, kk = idx & 31;
        int m = m0 + i, c = kk;
        float cur  = hs[(size_t)m*CC + c];
        float prev = ((m & (TT-1)) == 0) ? shift[(m>>12)*CC + c]
                                         : hs[(size_t)(m-1)*CC + c];
        px[u] = tf32r(cur + (prev - cur) * __ldg(&maa_x[c]));
    }
    #pragma unroll
    for (int u = 0; u < 20; u++) {
        int idx = tid + 256*u, kk = idx/160, n = idx - kk*160;
        pw[u] = tf32r(w1[(size_t)kk*160 + n]);
    }

    for (int k0 = 0; k0 < CC; k0 += 32) {
        __syncthreads();
        #pragma unroll
        for (int u = 0; u < 4; u++) {
            int idx = tid + 256*u;
            x_s[(idx >> 5)*36 + (idx & 31)] = px[u];
        }
        #pragma unroll
        for (int u = 0; u < 20; u++) {
            int idx = tid + 256*u, kk = idx/160, n = idx - kk*160;
            w1_s[kk*168 + n] = pw[u];
        }
        __syncthreads();
        const int kn = k0 + 32;
        if (kn < CC) {
            #pragma unroll
            for (int u = 0; u < 4; u++) {
                int idx = tid + 256*u, i = idx >> 5, kk = idx & 31;
                int m = m0 + i, c = kn + kk;
                float cur  = hs[(size_t)m*CC + c];
                float prev = ((m & (TT-1)) == 0) ? shift[(m>>12)*CC + c]
                                                 : hs[(size_t)(m-1)*CC + c];
                px[u] = tf32r(cur + (prev - cur) * __ldg(&maa_x[c]));
            }
            #pragma unroll
            for (int u = 0; u < 20; u++) {
                int idx = tid + 256*u, kk = idx/160, n = idx - kk*160;
                pw[u] = tf32r(w1[(size_t)(kn+kk)*160 + n]);
            }
        }
        #pragma unroll
        for (int ks = 0; ks < 4; ks++) {
            const float* Ab = x_s + (mt*16)*36 + ks*8;
            unsigned a0 = FB(Ab[gi*36 + t]);
            unsigned a1 = FB(Ab[(gi+8)*36 + t]);
            unsigned a2 = FB(Ab[gi*36 + t + 4]);
            unsigned a3 = FB(Ab[(gi+8)*36 + t + 4]);
            #pragma unroll
            for (int j = 0; j < 5; j++) {
                int n0 = ng*40 + j*8;
                unsigned b0 = FB(w1_s[(ks*8+t)*168 + n0 + gi]);
                unsigned b1 = FB(w1_s[(ks*8+t+4)*168 + n0 + gi]);
                mma8(acc[j], a0,a1,a2,a3, b0,b1);
            }
        }
    }
    const int mrow = m0 + mt*16 + gi;
    #pragma unroll
    for (int j = 0; j < 5; j++) {
        int n = ng*40 + j*8 + t*2;
        g_y[(size_t)mrow*160 + n]       = tf32r(tanhf(acc[j][0]));
        g_y[(size_t)mrow*160 + n + 1]   = tf32r(tanhf(acc[j][1]));
        g_y[(size_t)(mrow+8)*160 + n]   = tf32r(tanhf(acc[j][2]));
        g_y[(size_t)(mrow+8)*160 + n+1] = tf32r(tanhf(acc[j][3]));
    }
}

// =====================================================================
// K7: lx = hs[:, -1, :]
// =====================================================================
__global__ void k7_lx(const float* __restrict__ hs, float* __restrict__ out_lx)
{
    int idx = blockIdx.x*blockDim.x + threadIdx.x;   // B*C = 4096
    int b = idx >> 11, c = idx & 2047;
    out_lx[idx] = hs[((size_t)b*TT + (TT-1))*CC + c];
}

// =====================================================================
// KP v5: cp.async double-buffered, NO st_s (shuffle-based fragment
// conversion), NO persistent y buffer. smem = 2 stages = 66,080 B ->
// 3 blocks/SM -> grid 320 fits ONE wave (444 slots).
// Stage layout (floats): hs[129*36]=4644 | w2[32*40]=1280 | W[32*72]=2304
//                        | maa[32] -> stride 8260.
// =====================================================================
#define KP_SSTR  8260
#define KP_SMEM_FLOATS (2*KP_SSTR)
#define KP_SMEM_BYTES  (KP_SMEM_FLOATS*4)

__global__ __launch_bounds__(256,3) void kp_proj(
    const float* __restrict__ hs, const float* __restrict__ shift,
    const float* __restrict__ maa_w, const float* __restrict__ maa_k,
    const float* __restrict__ maa_v, const float* __restrict__ maa_r,
    const float* __restrict__ maa_g,
    const float* __restrict__ dw2,   const float* __restrict__ tdecay)
{
    extern __shared__ float sm[];
    float* stg = sm;                 // 2 stages

    const int tid  = threadIdx.x;
    const int lane = tid & 31, wid = tid >> 5;   // 8 warps, 16-token tiles
    const int gi   = lane >> 2, t = lane & 3;
    const int m0   = blockIdx.x * 128;
    const int f    = blockIdx.y;

    const float* mp = (f==0) ? maa_w : (f==1) ? maa_k : (f==2) ? maa_v
                     : (f==3) ? maa_r : maa_g;
    const float* w2r = g_w2r + (size_t)f*32*CC;
    const float* Wr  = g_Wr  + (size_t)f*CC*DD;

    const unsigned stg_sh = (unsigned)__cvta_generic_to_shared(stg);

    auto issue_stage = [&](int s, int c0n) {
        unsigned hb = stg_sh + (unsigned)(s*KP_SSTR)*4u;
        for (int idx = tid; idx < 1032; idx += 256) {
            int i = idx >> 3, c4 = (idx & 7) << 2;
            const float* src;
            if (i == 0 && (m0 & (TT-1)) == 0)
                src = shift + (size_t)(m0 >> 12)*CC + c0n + c4;
            else
                src = hs + (size_t)(m0 - 1 + i)*CC + c0n + c4;
            cpa16(hb + (unsigned)(i*36 + c4)*4u, src);
        }
        {
            int d = tid >> 3, c4 = (tid & 7) << 2;
            cpa16(hb + (unsigned)(4644 + d*40 + c4)*4u,
                  w2r + (size_t)d*CC + c0n + c4);
        }
        #pragma unroll
        for (int u = 0; u < 2; u++) {
            int idx = tid + u*256;
            int kk = idx >> 4, n4 = (idx & 15) << 2;
            cpa16(hb + (unsigned)(5924 + kk*72 + n4)*4u,
                  Wr + (size_t)(c0n + kk)*64 + n4);
        }
        if (tid < 8)
            cpa16(hb + (unsigned)(8228 + tid*4)*4u, mp + c0n + tid*4);
    };

    // prefetch chunk 0 into stage 0; stage y in stage-1 region meanwhile
    issue_stage(0, 0);
    CPA_COMMIT();
    {
        float* ytmp = stg + KP_SSTR;     // borrowed; dead after extraction
        for (int idx = tid; idx < 128*32; idx += 256) {
            int i = idx >> 5, kk = idx & 31;
            ytmp[i*36 + kk] = g_y[(size_t)(m0+i)*160 + f*32 + kk];
        }
        __syncthreads();
        // intentionally fall through: extract below, then loop's first
        // syncthreads (n=0) guards the overwrite by issue_stage(1,...)
    }
    unsigned ya[4][4];
    {
        float* ytmp = stg + KP_SSTR;
        #pragma unroll
        for (int ks = 0; ks < 4; ks++) {
            const float* Ab = ytmp + (wid*16)*36 + ks*8;
            ya[ks][0] = FB(Ab[gi*36 + t]);
            ya[ks][1] = FB(Ab[(gi+8)*36 + t]);
            ya[ks][2] = FB(Ab[gi*36 + t + 4]);
            ya[ks][3] = FB(Ab[(gi+8)*36 + t + 4]);
        }
    }

    const int p  = t & 1;                 // col parity
    const int s0 = (lane & ~3) | (t >> 1);       // src lane for cols t
    const int s4 = s0 + 2;                       // src lane for cols t+4

    float acc[8][4];
    #pragma unroll
    for (int j = 0; j < 8; j++)
        #pragma unroll
        for (int e = 0; e < 4; e++) acc[j][e] = 0.f;

    for (int n = 0; n < 64; n++) {
        const int s = n & 1;
        float* hs_s  = stg + s*KP_SSTR;
        float* w2_s  = hs_s + 4644;
        float* W_s   = hs_s + 5924;
        float* maa_s = hs_s + 8228;

        CPA_WAIT0();
        __syncthreads();
        if (n < 63) issue_stage(s ^ 1, (n + 1)*32);
        CPA_COMMIT();

        // phase A: m(16x32 per warp) = y(16x32) @ w2(32x32)
        float av[4][4];
        #pragma unroll
        for (int j = 0; j < 4; j++)
            #pragma unroll
            for (int e = 0; e < 4; e++) av[j][e] = 0.f;
        #pragma unroll
        for (int ks = 0; ks < 4; ks++) {
            #pragma unroll
            for (int j = 0; j < 4; j++) {
                unsigned b0 = FB(w2_s[(ks*8+t)*40   + j*8 + gi]);
                unsigned b1 = FB(w2_s[(ks*8+t+4)*40 + j*8 + gi]);
                mma8(av[j], ya[ks][0], ya[ks][1], ya[ks][2], ya[ks][3], b0, b1);
            }
        }
        // A build in registers (C-frag layout), tf32-rounded
        #pragma unroll
        for (int j = 0; j < 4; j++) {
            #pragma unroll
            for (int e = 0; e < 4; e++) {
                int r = wid*16 + gi + ((e & 2) ? 8 : 0);
                int c = j*8 + t*2 + (e & 1);
                float cur  = hs_s[(r+1)*36 + c];
                float prev = hs_s[r*36 + c];
                av[j][e] = tf32r(cur + (prev - cur)*(maa_s[c] + av[j][e]));
            }
        }

        // phase B: acc += A @ W ; A-fragments built by warp shuffles
        #pragma unroll
        for (int ks = 0; ks < 4; ks++) {
            float v00 = __shfl_sync(0xffffffffu, av[ks][0], s0);
            float v01 = __shfl_sync(0xffffffffu, av[ks][1], s0);
            float v02 = __shfl_sync(0xffffffffu, av[ks][2], s0);
            float v03 = __shfl_sync(0xffffffffu, av[ks][3], s0);
            float v40 = __shfl_sync(0xffffffffu, av[ks][0], s4);
            float v41 = __shfl_sync(0xffffffffu, av[ks][1], s4);
            float v42 = __shfl_sync(0xffffffffu, av[ks][2], s4);
            float v43 = __shfl_sync(0xffffffffu, av[ks][3], s4);
            unsigned a0 = FB(p ? v01 : v00);
            unsigned a1 = FB(p ? v03 : v02);
            unsigned a2 = FB(p ? v41 : v40);
            unsigned a3 = FB(p ? v43 : v42);
            #pragma unroll
            for (int j = 0; j < 8; j++) {
                unsigned b0 = FB(W_s[(ks*8+t)*72   + j*8 + gi]);
                unsigned b1 = FB(W_s[(ks*8+t+4)*72 + j*8 + gi]);
                mma8(acc[j], a0,a1,a2,a3, b0,b1);
            }
        }
    }

    if (f != 0) {
        #pragma unroll
        for (int j = 0; j < 8; j++) {
            #pragma unroll
            for (int e = 0; e < 4; e++) {
                int m = m0 + wid*16 + gi + ((e & 2) ? 8 : 0);
                int nn = j*8 + t*2 + (e & 1);
                size_t ad = (size_t)m*64 + nn;
                float x = acc[j][e];
                if      (f == 1) g_k[ad] = x;
                else if (f == 2) g_v[ad] = x;
                else if (f == 3) g_r[ad] = x;
                else             g_gv[ad] = x / (1.f + expf(-x));
            }
        }
    } else {
        // folded decay: T = tf32(tanh(acc)); g_w = -exp(tdecay + T@dw2)
        __syncthreads();                 // stages dead now
        float* T_s  = sm;                // [128][68] = 8704
        float* d2_s = sm + 8704;         // [64][72]  = 4608
        float* td_s = sm + 13312;        // [64]
        #pragma unroll
        for (int j = 0; j < 8; j++) {
            #pragma unroll
            for (int e = 0; e < 4; e++) {
                int r = wid*16 + gi + ((e & 2) ? 8 : 0);
                int c = j*8 + t*2 + (e & 1);
                T_s[r*68 + c] = tf32r(tanhf(acc[j][e]));
            }
        }
        for (int idx = tid; idx < 4096; idx += 256) {
            int d = idx >> 6, nn = idx & 63;
            d2_s[d*72 + nn] = tf32r(dw2[idx]);
        }
        if (tid < 64) td_s[tid] = tdecay[tid];
        __syncthreads();

        float acc2[8][4];
        #pragma unroll
        for (int j = 0; j < 8; j++)
            #pragma unroll
            for (int e = 0; e < 4; e++) acc2[j][e] = 0.f;
        #pragma unroll
        for (int ks = 0; ks < 8; ks++) {
            const float* Ab = T_s + (wid*16)*68 + ks*8;
            unsigned a0 = FB(Ab[gi*68 + t]);
            unsigned a1 = FB(Ab[(gi+8)*68 + t]);
            unsigned a2 = FB(Ab[gi*68 + t + 4]);
            unsigned a3 = FB(Ab[(gi+8)*68 + t + 4]);
            #pragma unroll
            for (int j = 0; j < 8; j++) {
                unsigned b0 = FB(d2_s[(ks*8+t)*72 + j*8 + gi]);
                unsigned b1 = FB(d2_s[(ks*8+t+4)*72 + j*8 + gi]);
                mma8(acc2[j], a0,a1,a2,a3, b0,b1);
            }
        }
        #pragma unroll
        for (int j = 0; j < 8; j++) {
            #pragma unroll
            for (int e = 0; e < 4; e++) {
                int m = m0 + wid*16 + gi + ((e & 2) ? 8 : 0);
                int nn = j*8 + t*2 + (e & 1);
                g_w[(size_t)m*64 + nn] = -expf(td_s[nn] + acc2[j][e]);
            }
        }
    }
}

// =====================================================================
// K3 (proven)
// =====================================================================
__global__ __launch_bounds__(256,1) void k3_chunk()
{
    __shared__ float k_s[32*64], v_s[32*64], cum_s[32*64], kh_s[32*64];
    const int bc   = blockIdx.x;
    const int tok0 = bc * 32;
    const int tid  = threadIdx.x;

    for (int idx = tid; idx < 2048; idx += 256) {
        size_t g = (size_t)tok0*64 + idx;
        k_s[idx]   = g_k[g];
        v_s[idx]   = g_v[g];
        cum_s[idx] = g_w[g];
    }
    __syncthreads();
    if (tid < 64) {
        float c = 0.f;
        for (int i = 0; i < 32; i++) { c += cum_s[i*64 + tid]; cum_s[i*64 + tid] = c; }
        g_P[bc*64 + tid] = expf(c);
        for (int i = 0; i < 32; i++)
            kh_s[i*64 + tid] = k_s[i*64 + tid] * expf(c - cum_s[i*64 + tid]);
    }
    __syncthreads();
    for (int it = 0; it < 16; it++) {
        int e  = tid + 256*it;
        int dk = e >> 6, dv = e & 63;
        float s = 0.f;
        #pragma unroll
        for (int i = 0; i < 32; i++)
            s += kh_s[i*64 + dk] * v_s[i*64 + dv];
        g_M[(size_t)bc*4096 + e] = s;
    }
}

// =====================================================================
// K4 (proven): inter-chunk scan, prefetch depth 32
// =====================================================================
__global__ __launch_bounds__(256,1) void k4_scan(
    const float* __restrict__ wkv0, float* __restrict__ out_sf)
{
    const int e  = blockIdx.x*256 + threadIdx.x;
    const int b  = e >> 12, eb = e & 4095, dk = eb >> 6;
    float sv = wkv0[e];
    const float* Mp = g_M + (size_t)b*NCH*4096 + eb;
    const float* Pp = g_P + b*NCH*64 + dk;
    float*       Sp = g_S + (size_t)b*NCH*4096 + eb;

    float mq[32], pq[32];
    #pragma unroll
    for (int q = 0; q < 32; q++) { mq[q] = Mp[(size_t)q*4096]; pq[q] = Pp[q*64]; }

    for (int c = 0; c < NCH; c += 32) {
        #pragma unroll
        for (int q = 0; q < 32; q++) {
            Sp[(size_t)(c+q)*4096] = sv;
            sv = sv*pq[q] + mq[q];
            int cn = c + q + 32;
            if (cn < NCH) { mq[q] = Mp[(size_t)cn*4096]; pq[q] = Pp[cn*64]; }
        }
    }
    out_sf[e] = sv;
}

// =====================================================================
// K5 (proven)
// =====================================================================
#define K5_SMEM_FLOATS (4*(32*65) + 64*65 + 32*33 + 32)
#define K5_SMEM_BYTES  (K5_SMEM_FLOATS*4)

__global__ __launch_bounds__(256,1) void k5_intra(const float* __restrict__ faaaa)
{
    extern __shared__ float sm5[];
    float* r_s    = sm5;
    float* k_s    = r_s   + 32*65;
    float* v_s    = k_s   + 32*65;
    float* cum_s  = v_s   + 32*65;
    float* S_s    = cum_s + 32*65;
    float* sc_s   = S_s   + 64*65;
    float* diag_s = sc_s  + 32*33;

    const int bc   = blockIdx.x;
    const int tok0 = bc * 32;
    const int tid  = threadIdx.x;

    for (int idx = tid; idx < 2048; idx += 256) {
        int i = idx >> 6, d = idx & 63;
        size_t g = (size_t)tok0*64 + idx;
        r_s[i*65 + d]   = g_r[g];
        k_s[i*65 + d]   = g_k[g];
        v_s[i*65 + d]   = g_v[g];
        cum_s[i*65 + d] = g_w[g];
    }
    for (int idx = tid; idx < 4096; idx += 256) {
        int dk = idx >> 6, dv = idx & 63;
        S_s[dk*65 + dv] = g_S[(size_t)bc*4096 + idx];
    }
    __syncthreads();
    if (tid < 64) {
        float c = 0.f;
        for (int i = 0; i < 32; i++) { c += cum_s[i*65 + tid]; cum_s[i*65 + tid] = c; }
    }
    __syncthreads();
    if (tid < 32) {
        float s = 0.f;
        #pragma unroll
        for (int d = 0; d < 64; d++)
            s += r_s[tid*65 + d] * __ldg(&faaaa[d]) * k_s[tid*65 + d];
        diag_s[tid] = s;
    }
    __syncthreads();
    for (int idx = tid; idx < 2048; idx += 256) {
        int i = idx >> 6, d = idx & 63;
        float ce = (i == 0) ? 0.f : cum_s[(i-1)*65 + d];
        r_s[i*65 + d] *= expf(ce);
        k_s[i*65 + d] *= expf(-cum_s[i*65 + d]);
    }
    __syncthreads();
    #pragma unroll
    for (int q = 0; q < 4; q++) {
        int idx = tid + 256*q;
        int i = idx >> 5, j = idx & 31;
        float val;
        if (j < i) {
            float s = 0.f;
            #pragma unroll
            for (int d = 0; d < 64; d++)
                s += r_s[i*65 + d] * k_s[j*65 + d];
            val = s;
        } else {
            val = (j == i) ? diag_s[i] : 0.f;
        }
        sc_s[i*33 + j] = val;
    }
    __syncthreads();
    #pragma unroll
    for (int q = 0; q < 8; q++) {
        int idx = tid + 256*q;
        int i = idx >> 6, dv = idx & 63;
        float o = 0.f;
        #pragma unroll
        for (int j = 0; j < 32; j++)
            o += sc_s[i*33 + j] * v_s[j*65 + dv];
        #pragma unroll
        for (int d = 0; d < 64; d++)
            o += r_s[i*65 + d] * S_s[d*65 + dv];
        g_o[(size_t)tok0*64 + idx] = o;
    }
}

// =====================================================================
// K6 (proven): out = (o * g) @ W_o via tf32 mma, 128x128 tile
// =====================================================================
#define K6_SMEM_BYTES ((128*68 + 64*136)*4)
__global__ __launch_bounds__(256,1) void k6_out(
    const float* __restrict__ Wo, float* __restrict__ out)
{
    extern __shared__ float sm6[];
    float* a_s = sm6;
    float* b_s = a_s + 128*68;

    const int tid  = threadIdx.x;
    const int lane = tid & 31, wid = tid >> 5;
    const int gi   = lane >> 2, t = lane & 3;
    const int bm = blockIdx.x * 128, bn = blockIdx.y * 128;

    for (int idx = tid; idx < 8192; idx += 256) {
        int i = idx >> 6, d = idx & 63;
        size_t g = (size_t)(bm+i)*64 + d;
        a_s[i*68 + d] = tf32r(g_o[g] * g_gv[g]);
    }
    for (int idx = tid; idx < 8192; idx += 256) {
        int dd = idx >> 7, n = idx & 127;
        b_s[dd*136 + n] = tf32r(Wo[(size_t)dd*CC + bn + n]);
    }
    __syncthreads();

    const int rb = (wid & 3) * 32;
    const int n0 = (wid >> 2) * 64;
    float acc[2][8][4];
    #pragma unroll
    for (int mi = 0; mi < 2; mi++)
        #pragma unroll
        for (int j = 0; j < 8; j++)
            #pragma unroll
            for (int e = 0; e < 4; e++) acc[mi][j][e] = 0.f;

    #pragma unroll
    for (int ks = 0; ks < 8; ks++) {
        unsigned a[2][4];
        #pragma unroll
        for (int mi = 0; mi < 2; mi++) {
            const float* Ab = a_s + (rb + mi*16)*68 + ks*8;
            a[mi][0] = FB(Ab[gi*68 + t]);
            a[mi][1] = FB(Ab[(gi+8)*68 + t]);
            a[mi][2] = FB(Ab[gi*68 + t + 4]);
            a[mi][3] = FB(Ab[(gi+8)*68 + t + 4]);
        }
        #pragma unroll
        for (int j = 0; j < 8; j++) {
            unsigned b0 = FB(b_s[(ks*8+t)*136 + n0 + j*8 + gi]);
            unsigned b1 = FB(b_s[(ks*8+t+4)*136 + n0 + j*8 + gi]);
            mma8(acc[0][j], a[0][0],a[0][1],a[0][2],a[0][3], b0,b1);
            mma8(acc[1][j], a[1][0],a[1][1],a[1][2],a[1][3], b0,b1);
        }
    }
    #pragma unroll
    for (int mi = 0; mi < 2; mi++)
        #pragma unroll
        for (int j = 0; j < 8; j++) {
            int m = bm + rb + mi*16 + gi;
            int n = bn + n0 + j*8 + t*2;
            out[(size_t)m*CC + n]       = acc[mi][j][0];
            out[(size_t)m*CC + n + 1]   = acc[mi][j][1];
            out[(size_t)(m+8)*CC + n]   = acc[mi][j][2];
            out[(size_t)(m+8)*CC + n+1] = acc[mi][j][3];
        }
}

// =====================================================================
extern "C" void kernel_launch(void* const* d_in, const int* in_sizes, int n_in,
                              void* d_out, int out_size)
{
    (void)in_sizes; (void)n_in; (void)out_size;
    const float* hs     = (const float*)d_in[0];
    const float* shift  = (const float*)d_in[1];
    const float* wkv0   = (const float*)d_in[2];
    const float* maa_x  = (const float*)d_in[3];
    const float* maa_w  = (const float*)d_in[4];
    const float* maa_k  = (const float*)d_in[5];
    const float* maa_v  = (const float*)d_in[6];
    const float* maa_r  = (const float*)d_in[7];
    const float* maa_g  = (const float*)d_in[8];
    const float* w1     = (const float*)d_in[9];
    const float* w2     = (const float*)d_in[10];
    const float* tdecay = (const float*)d_in[11];
    const float* dw1    = (const float*)d_in[12];
    const float* dw2    = (const float*)d_in[13];
    const float* faaaa  = (const float*)d_in[14];
    const float* Wr     = (const float*)d_in[15];
    const float* Wk     = (const float*)d_in[16];
    const float* Wv     = (const float*)d_in[17];
    const float* Wg     = (const float*)d_in[18];
    const float* Wo     = (const float*)d_in[19];
    float* out = (float*)d_out;

    const size_t OFF_LX = (size_t)BQ*TT*CC;
    const size_t OFF_SF = OFF_LX + (size_t)BQ*CC;

    cudaFuncSetAttribute(kp_proj,  cudaFuncAttributeMaxDynamicSharedMemorySize, KP_SMEM_BYTES);
    cudaFuncSetAttribute(k5_intra, cudaFuncAttributeMaxDynamicSharedMemorySize, K5_SMEM_BYTES);
    cudaFuncSetAttribute(k6_out,   cudaFuncAttributeMaxDynamicSharedMemorySize, K6_SMEM_BYTES);

    // kp stays at launch index 3 for ncu sampling.
    kprep   <<<512, 256>>>(w2, dw1, Wk, Wv, Wr, Wg);               // idx 0
    k1_mix  <<<MTOK/32, 256>>>(hs, shift, maa_x, w1);              // idx 1
    k7_lx   <<<8, 512>>>(hs, out + OFF_LX);                        // idx 2
    kp_proj <<<dim3(MTOK/128, 5), 256, KP_SMEM_BYTES>>>(hs, shift, // idx 3
                                                        maa_w, maa_k, maa_v,
                                                        maa_r, maa_g,
                                                        dw2, tdecay);
    k3_chunk<<<BQ*NCH, 256>>>();                                   // idx 4
    k4_scan <<<32, 256>>>(wkv0, out + OFF_SF);                     // idx 5
    k5_intra<<<BQ*NCH, 256, K5_SMEM_BYTES>>>(faaaa);               // idx 6
    k6_out  <<<dim3(MTOK/128, CC/128), 256, K6_SMEM_BYTES>>>(Wo, out);  // idx 7
}

// round 15
// speedup vs baseline: 1.6179x; 1.1882x over previous
#include <cuda_runtime.h>
#include <math.h>

// Problem constants
#define BQ   2
#define TT   4096
#define CC   2048
#define DD   64
#define MTOK (BQ*TT)      // 8192 tokens
#define LCH  32
#define NCH  (TT/LCH)     // 128 chunks per batch

// ---------------- device scratch ----------------
__device__ __align__(16) float g_y [MTOK*160];       // tanh mix features (tf32-rounded)
__device__ __align__(16) float g_w1r[CC*160];        // tf32-rounded w1
__device__ __align__(16) float g_w2r[160*CC];        // tf32-rounded w2
__device__ __align__(16) float g_Wr [5*CC*DD];       // tf32-rounded {dw1,Wk,Wv,Wr,Wg}
__device__ __align__(16) float g_r [MTOK*DD];
__device__ __align__(16) float g_k [MTOK*DD];
__device__ __align__(16) float g_v [MTOK*DD];
__device__ __align__(16) float g_gv[MTOK*DD];
__device__ __align__(16) float g_w [MTOK*DD];
__device__ __align__(16) float g_M [BQ*NCH*DD*DD];
__device__ __align__(16) float g_S [BQ*NCH*DD*DD];
__device__ __align__(16) float g_P [BQ*NCH*DD];
__device__ __align__(16) float g_o [MTOK*DD];

// ---------------- helpers ----------------
__device__ __forceinline__ float tf32r(float x) {
    unsigned u;
    asm("cvt.rna.tf32.f32 %0, %1;" : "=r"(u) : "f"(x));
    return __uint_as_float(u);
}
__device__ __forceinline__ void mma8(float* d,
    unsigned a0, unsigned a1, unsigned a2, unsigned a3,
    unsigned b0, unsigned b1)
{
    asm volatile(
        "mma.sync.aligned.m16n8k8.row.col.f32.tf32.tf32.f32 "
        "{%0,%1,%2,%3}, {%4,%5,%6,%7}, {%8,%9}, {%0,%1,%2,%3};"
        : "+f"(d[0]), "+f"(d[1]), "+f"(d[2]), "+f"(d[3])
        : "r"(a0), "r"(a1), "r"(a2), "r"(a3), "r"(b0), "r"(b1));
}
__device__ __forceinline__ void cpa16(unsigned dst, const float* src) {
    asm volatile("cp.async.ca.shared.global [%0], [%1], 16;" :: "r"(dst), "l"(src));
}
#define CPA_COMMIT() asm volatile("cp.async.commit_group;")
#define CPA_WAIT0()  asm volatile("cp.async.wait_group 0;")
#define FB(x) __float_as_uint(x)

// =====================================================================
// KPREP1: tf32-round w1
// =====================================================================
__global__ __launch_bounds__(256) void kprep1(const float* __restrict__ w1)
{
    int i0 = blockIdx.x*256 + threadIdx.x;
    for (int idx = i0; idx < CC*160; idx += gridDim.x*256)
        g_w1r[idx] = tf32r(w1[idx]);
}

// =====================================================================
// KPREP2: tf32-round w2 and the five 2048x64 weights
// =====================================================================
__global__ __launch_bounds__(256) void kprep2(
    const float* __restrict__ w2,  const float* __restrict__ dw1,
    const float* __restrict__ Wk,  const float* __restrict__ Wv,
    const float* __restrict__ Wr_, const float* __restrict__ Wg)
{
    int i0 = blockIdx.x*256 + threadIdx.x;
    for (int idx = i0; idx < 160*CC; idx += gridDim.x*256)
        g_w2r[idx] = tf32r(w2[idx]);
    for (int idx = i0; idx < 5*CC*DD; idx += gridDim.x*256) {
        int f = idx / (CC*DD), r = idx - f*(CC*DD);
        const float* Wf = (f==0) ? dw1 : (f==1) ? Wk : (f==2) ? Wv
                         : (f==3) ? Wr_ : Wg;
        g_Wr[idx] = tf32r(Wf[r]);
    }
}

// =====================================================================
// K7: lx = hs[:, -1, :]
// =====================================================================
__global__ void k7_lx(const float* __restrict__ hs, float* __restrict__ out_lx)
{
    int idx = blockIdx.x*blockDim.x + threadIdx.x;   // B*C = 4096
    int b = idx >> 11, c = idx & 2047;
    out_lx[idx] = hs[((size_t)b*TT + (TT-1))*CC + c];
}

// =====================================================================
// K1 v3: cp.async double-buffered. Per 32-token block, N=160.
// Stage (floats): hs[33*36]=1188 | w1[32*168]=5376 -> stride 6564.
// smem = 2*6564*4 = 52512 B -> 3 blocks/SM (one wave at grid 256 anyway).
// x = tf32r(cur + (prev-cur)*maa_x) computed at fragment-build time
// from the raw hs tile (bit-identical to v2's precomputed x_s).
// =====================================================================
#define K1_SSTR  6564
#define K1_SMEM_BYTES (2*K1_SSTR*4)

__global__ __launch_bounds__(256,3) void k1_mix(
    const float* __restrict__ hs, const float* __restrict__ shift,
    const float* __restrict__ maa_x)
{
    extern __shared__ float sm1[];
    float* stg = sm1;

    const int tid  = threadIdx.x;
    const int lane = tid & 31, wid = tid >> 5;
    const int gi   = lane >> 2, t = lane & 3;
    const int m0   = blockIdx.x * 32;
    const int mt   = wid & 1;          // 16-row tile
    const int ng   = wid >> 1;         // col group of 40

    const unsigned stg_sh = (unsigned)__cvta_generic_to_shared(stg);

    auto issue_stage = [&](int s, int k0n) {
        unsigned hb = stg_sh + (unsigned)(s*K1_SSTR)*4u;
        // hs rows m0-1..m0+31, 32 cols: 264 x 16B
        for (int idx = tid; idx < 264; idx += 256) {
            int i = idx >> 3, c4 = (idx & 7) << 2;
            const float* src;
            if (i == 0 && (m0 & (TT-1)) == 0)
                src = shift + (size_t)(m0 >> 12)*CC + k0n + c4;
            else
                src = hs + (size_t)(m0 - 1 + i)*CC + k0n + c4;
            cpa16(hb + (unsigned)(i*36 + c4)*4u, src);
        }
        // w1 chunk: 32 x 160 = 1280 x 16B
        for (int idx = tid; idx < 1280; idx += 256) {
            int kk = idx / 40, n4 = (idx - kk*40) << 2;
            cpa16(hb + (unsigned)(1188 + kk*168 + n4)*4u,
                  g_w1r + (size_t)(k0n + kk)*160 + n4);
        }
    };

    issue_stage(0, 0);
    CPA_COMMIT();

    float acc[5][4];
    #pragma unroll
    for (int j = 0; j < 5; j++)
        #pragma unroll
        for (int e = 0; e < 4; e++) acc[j][e] = 0.f;

    const int r0 = mt*16 + gi;         // A rows for this lane
    const int r1 = r0 + 8;

    for (int n = 0; n < 64; n++) {
        const int s = n & 1;
        float* hs_s = stg + s*K1_SSTR;
        float* w1_s = hs_s + 1188;
        const int k0 = n*32;

        CPA_WAIT0();
        __syncthreads();
        if (n < 63) issue_stage(s ^ 1, (n + 1)*32);
        CPA_COMMIT();

        #pragma unroll
        for (int ks = 0; ks < 4; ks++) {
            int cl0 = ks*8 + t, cl1 = cl0 + 4;
            float ma0 = __ldg(&maa_x[k0 + cl0]);
            float ma1 = __ldg(&maa_x[k0 + cl1]);
            float c00 = hs_s[(r0+1)*36 + cl0], p00 = hs_s[r0*36 + cl0];
            float c10 = hs_s[(r1+1)*36 + cl0], p10 = hs_s[r1*36 + cl0];
            float c01 = hs_s[(r0+1)*36 + cl1], p01 = hs_s[r0*36 + cl1];
            float c11 = hs_s[(r1+1)*36 + cl1], p11 = hs_s[r1*36 + cl1];
            unsigned a0 = FB(tf32r(c00 + (p00 - c00) * ma0));
            unsigned a1 = FB(tf32r(c10 + (p10 - c10) * ma0));
            unsigned a2 = FB(tf32r(c01 + (p01 - c01) * ma1));
            unsigned a3 = FB(tf32r(c11 + (p11 - c11) * ma1));
            #pragma unroll
            for (int j = 0; j < 5; j++) {
                int n0 = ng*40 + j*8;
                unsigned b0 = FB(w1_s[(ks*8+t)*168 + n0 + gi]);
                unsigned b1 = FB(w1_s[(ks*8+t+4)*168 + n0 + gi]);
                mma8(acc[j], a0,a1,a2,a3, b0,b1);
            }
        }
    }
    const int mrow = m0 + mt*16 + gi;
    #pragma unroll
    for (int j = 0; j < 5; j++) {
        int n = ng*40 + j*8 + t*2;
        g_y[(size_t)mrow*160 + n]       = tf32r(tanhf(acc[j][0]));
        g_y[(size_t)mrow*160 + n + 1]   = tf32r(tanhf(acc[j][1]));
        g_y[(size_t)(mrow+8)*160 + n]   = tf32r(tanhf(acc[j][2]));
        g_y[(size_t)(mrow+8)*160 + n+1] = tf32r(tanhf(acc[j][3]));
    }
}

// =====================================================================
// KP v5 (R14 proven, byte-identical)
// =====================================================================
#define KP_SSTR  8260
#define KP_SMEM_FLOATS (2*KP_SSTR)
#define KP_SMEM_BYTES  (KP_SMEM_FLOATS*4)

__global__ __launch_bounds__(256,3) void kp_proj(
    const float* __restrict__ hs, const float* __restrict__ shift,
    const float* __restrict__ maa_w, const float* __restrict__ maa_k,
    const float* __restrict__ maa_v, const float* __restrict__ maa_r,
    const float* __restrict__ maa_g,
    const float* __restrict__ dw2,   const float* __restrict__ tdecay)
{
    extern __shared__ float sm[];
    float* stg = sm;

    const int tid  = threadIdx.x;
    const int lane = tid & 31, wid = tid >> 5;
    const int gi   = lane >> 2, t = lane & 3;
    const int m0   = blockIdx.x * 128;
    const int f    = blockIdx.y;

    const float* mp = (f==0) ? maa_w : (f==1) ? maa_k : (f==2) ? maa_v
                     : (f==3) ? maa_r : maa_g;
    const float* w2r = g_w2r + (size_t)f*32*CC;
    const float* Wr  = g_Wr  + (size_t)f*CC*DD;

    const unsigned stg_sh = (unsigned)__cvta_generic_to_shared(stg);

    auto issue_stage = [&](int s, int c0n) {
        unsigned hb = stg_sh + (unsigned)(s*KP_SSTR)*4u;
        for (int idx = tid; idx < 1032; idx += 256) {
            int i = idx >> 3, c4 = (idx & 7) << 2;
            const float* src;
            if (i == 0 && (m0 & (TT-1)) == 0)
                src = shift + (size_t)(m0 >> 12)*CC + c0n + c4;
            else
                src = hs + (size_t)(m0 - 1 + i)*CC + c0n + c4;
            cpa16(hb + (unsigned)(i*36 + c4)*4u, src);
        }
        {
            int d = tid >> 3, c4 = (tid & 7) << 2;
            cpa16(hb + (unsigned)(4644 + d*40 + c4)*4u,
                  w2r + (size_t)d*CC + c0n + c4);
        }
        #pragma unroll
        for (int u = 0; u < 2; u++) {
            int idx = tid + u*256;
            int kk = idx >> 4, n4 = (idx & 15) << 2;
            cpa16(hb + (unsigned)(5924 + kk*72 + n4)*4u,
                  Wr + (size_t)(c0n + kk)*64 + n4);
        }
        if (tid < 8)
            cpa16(hb + (unsigned)(8228 + tid*4)*4u, mp + c0n + tid*4);
    };

    issue_stage(0, 0);
    CPA_COMMIT();
    {
        float* ytmp = stg + KP_SSTR;
        for (int idx = tid; idx < 128*32; idx += 256) {
            int i = idx >> 5, kk = idx & 31;
            ytmp[i*36 + kk] = g_y[(size_t)(m0+i)*160 + f*32 + kk];
        }
        __syncthreads();
    }
    unsigned ya[4][4];
    {
        float* ytmp = stg + KP_SSTR;
        #pragma unroll
        for (int ks = 0; ks < 4; ks++) {
            const float* Ab = ytmp + (wid*16)*36 + ks*8;
            ya[ks][0] = FB(Ab[gi*36 + t]);
            ya[ks][1] = FB(Ab[(gi+8)*36 + t]);
            ya[ks][2] = FB(Ab[gi*36 + t + 4]);
            ya[ks][3] = FB(Ab[(gi+8)*36 + t + 4]);
        }
    }

    const int p  = t & 1;
    const int s0 = (lane & ~3) | (t >> 1);
    const int s4 = s0 + 2;

    float acc[8][4];
    #pragma unroll
    for (int j = 0; j < 8; j++)
        #pragma unroll
        for (int e = 0; e < 4; e++) acc[j][e] = 0.f;

    for (int n = 0; n < 64; n++) {
        const int s = n & 1;
        float* hs_s  = stg + s*KP_SSTR;
        float* w2_s  = hs_s + 4644;
        float* W_s   = hs_s + 5924;
        float* maa_s = hs_s + 8228;

        CPA_WAIT0();
        __syncthreads();
        if (n < 63) issue_stage(s ^ 1, (n + 1)*32);
        CPA_COMMIT();

        float av[4][4];
        #pragma unroll
        for (int j = 0; j < 4; j++)
            #pragma unroll
            for (int e = 0; e < 4; e++) av[j][e] = 0.f;
        #pragma unroll
        for (int ks = 0; ks < 4; ks++) {
            #pragma unroll
            for (int j = 0; j < 4; j++) {
                unsigned b0 = FB(w2_s[(ks*8+t)*40   + j*8 + gi]);
                unsigned b1 = FB(w2_s[(ks*8+t+4)*40 + j*8 + gi]);
                mma8(av[j], ya[ks][0], ya[ks][1], ya[ks][2], ya[ks][3], b0, b1);
            }
        }
        #pragma unroll
        for (int j = 0; j < 4; j++) {
            #pragma unroll
            for (int e = 0; e < 4; e++) {
                int r = wid*16 + gi + ((e & 2) ? 8 : 0);
                int c = j*8 + t*2 + (e & 1);
                float cur  = hs_s[(r+1)*36 + c];
                float prev = hs_s[r*36 + c];
                av[j][e] = tf32r(cur + (prev - cur)*(maa_s[c] + av[j][e]));
            }
        }

        #pragma unroll
        for (int ks = 0; ks < 4; ks++) {
            float v00 = __shfl_sync(0xffffffffu, av[ks][0], s0);
            float v01 = __shfl_sync(0xffffffffu, av[ks][1], s0);
            float v02 = __shfl_sync(0xffffffffu, av[ks][2], s0);
            float v03 = __shfl_sync(0xffffffffu, av[ks][3], s0);
            float v40 = __shfl_sync(0xffffffffu, av[ks][0], s4);
            float v41 = __shfl_sync(0xffffffffu, av[ks][1], s4);
            float v42 = __shfl_sync(0xffffffffu, av[ks][2], s4);
            float v43 = __shfl_sync(0xffffffffu, av[ks][3], s4);
            unsigned a0 = FB(p ? v01 : v00);
            unsigned a1 = FB(p ? v03 : v02);
            unsigned a2 = FB(p ? v41 : v40);
            unsigned a3 = FB(p ? v43 : v42);
            #pragma unroll
            for (int j = 0; j < 8; j++) {
                unsigned b0 = FB(W_s[(ks*8+t)*72   + j*8 + gi]);
                unsigned b1 = FB(W_s[(ks*8+t+4)*72 + j*8 + gi]);
                mma8(acc[j], a0,a1,a2,a3, b0,b1);
            }
        }
    }

    if (f != 0) {
        #pragma unroll
        for (int j = 0; j < 8; j++) {
            #pragma unroll
            for (int e = 0; e < 4; e++) {
                int m = m0 + wid*16 + gi + ((e & 2) ? 8 : 0);
                int nn = j*8 + t*2 + (e & 1);
                size_t ad = (size_t)m*64 + nn;
                float x = acc[j][e];
                if      (f == 1) g_k[ad] = x;
                else if (f == 2) g_v[ad] = x;
                else if (f == 3) g_r[ad] = x;
                else             g_gv[ad] = x / (1.f + expf(-x));
            }
        }
    } else {
        __syncthreads();
        float* T_s  = sm;                // [128][68] = 8704
        float* d2_s = sm + 8704;         // [64][72]  = 4608
        float* td_s = sm + 13312;        // [64]
        #pragma unroll
        for (int j = 0; j < 8; j++) {
            #pragma unroll
            for (int e = 0; e < 4; e++) {
                int r = wid*16 + gi + ((e & 2) ? 8 : 0);
                int c = j*8 + t*2 + (e & 1);
                T_s[r*68 + c] = tf32r(tanhf(acc[j][e]));
            }
        }
        for (int idx = tid; idx < 4096; idx += 256) {
            int d = idx >> 6, nn = idx & 63;
            d2_s[d*72 + nn] = tf32r(dw2[idx]);
        }
        if (tid < 64) td_s[tid] = tdecay[tid];
        __syncthreads();

        float acc2[8][4];
        #pragma unroll
        for (int j = 0; j < 8; j++)
            #pragma unroll
            for (int e = 0; e < 4; e++) acc2[j][e] = 0.f;
        #pragma unroll
        for (int ks = 0; ks < 8; ks++) {
            const float* Ab = T_s + (wid*16)*68 + ks*8;
            unsigned a0 = FB(Ab[gi*68 + t]);
            unsigned a1 = FB(Ab[(gi+8)*68 + t]);
            unsigned a2 = FB(Ab[gi*68 + t + 4]);
            unsigned a3 = FB(Ab[(gi+8)*68 + t + 4]);
            #pragma unroll
            for (int j = 0; j < 8; j++) {
                unsigned b0 = FB(d2_s[(ks*8+t)*72 + j*8 + gi]);
                unsigned b1 = FB(d2_s[(ks*8+t+4)*72 + j*8 + gi]);
                mma8(acc2[j], a0,a1,a2,a3, b0,b1);
            }
        }
        #pragma unroll
        for (int j = 0; j < 8; j++) {
            #pragma unroll
            for (int e = 0; e < 4; e++) {
                int m = m0 + wid*16 + gi + ((e & 2) ? 8 : 0);
                int nn = j*8 + t*2 + (e & 1);
                g_w[(size_t)m*64 + nn] = -expf(td_s[nn] + acc2[j][e]);
            }
        }
    }
}

// =====================================================================
// K3 (proven)
// =====================================================================
__global__ __launch_bounds__(256,1) void k3_chunk()
{
    __shared__ float k_s[32*64], v_s[32*64], cum_s[32*64], kh_s[32*64];
    const int bc   = blockIdx.x;
    const int tok0 = bc * 32;
    const int tid  = threadIdx.x;

    for (int idx = tid; idx < 2048; idx += 256) {
        size_t g = (size_t)tok0*64 + idx;
        k_s[idx]   = g_k[g];
        v_s[idx]   = g_v[g];
        cum_s[idx] = g_w[g];
    }
    __syncthreads();
    if (tid < 64) {
        float c = 0.f;
        for (int i = 0; i < 32; i++) { c += cum_s[i*64 + tid]; cum_s[i*64 + tid] = c; }
        g_P[bc*64 + tid] = expf(c);
        for (int i = 0; i < 32; i++)
            kh_s[i*64 + tid] = k_s[i*64 + tid] * expf(c - cum_s[i*64 + tid]);
    }
    __syncthreads();
    for (int it = 0; it < 16; it++) {
        int e  = tid + 256*it;
        int dk = e >> 6, dv = e & 63;
        float s = 0.f;
        #pragma unroll
        for (int i = 0; i < 32; i++)
            s += kh_s[i*64 + dk] * v_s[i*64 + dv];
        g_M[(size_t)bc*4096 + e] = s;
    }
}

// =====================================================================
// K4 (proven): inter-chunk scan, prefetch depth 32
// =====================================================================
__global__ __launch_bounds__(256,1) void k4_scan(
    const float* __restrict__ wkv0, float* __restrict__ out_sf)
{
    const int e  = blockIdx.x*256 + threadIdx.x;
    const int b  = e >> 12, eb = e & 4095, dk = eb >> 6;
    float sv = wkv0[e];
    const float* Mp = g_M + (size_t)b*NCH*4096 + eb;
    const float* Pp = g_P + b*NCH*64 + dk;
    float*       Sp = g_S + (size_t)b*NCH*4096 + eb;

    float mq[32], pq[32];
    #pragma unroll
    for (int q = 0; q < 32; q++) { mq[q] = Mp[(size_t)q*4096]; pq[q] = Pp[q*64]; }

    for (int c = 0; c < NCH; c += 32) {
        #pragma unroll
        for (int q = 0; q < 32; q++) {
            Sp[(size_t)(c+q)*4096] = sv;
            sv = sv*pq[q] + mq[q];
            int cn = c + q + 32;
            if (cn < NCH) { mq[q] = Mp[(size_t)cn*4096]; pq[q] = Pp[cn*64]; }
        }
    }
    out_sf[e] = sv;
}

// =====================================================================
// K5 (proven)
// =====================================================================
#define K5_SMEM_FLOATS (4*(32*65) + 64*65 + 32*33 + 32)
#define K5_SMEM_BYTES  (K5_SMEM_FLOATS*4)

__global__ __launch_bounds__(256,1) void k5_intra(const float* __restrict__ faaaa)
{
    extern __shared__ float sm5[];
    float* r_s    = sm5;
    float* k_s    = r_s   + 32*65;
    float* v_s    = k_s   + 32*65;
    float* cum_s  = v_s   + 32*65;
    float* S_s    = cum_s + 32*65;
    float* sc_s   = S_s   + 64*65;
    float* diag_s = sc_s  + 32*33;

    const int bc   = blockIdx.x;
    const int tok0 = bc * 32;
    const int tid  = threadIdx.x;

    for (int idx = tid; idx < 2048; idx += 256) {
        int i = idx >> 6, d = idx & 63;
        size_t g = (size_t)tok0*64 + idx;
        r_s[i*65 + d]   = g_r[g];
        k_s[i*65 + d]   = g_k[g];
        v_s[i*65 + d]   = g_v[g];
        cum_s[i*65 + d] = g_w[g];
    }
    for (int idx = tid; idx < 4096; idx += 256) {
        int dk = idx >> 6, dv = idx & 63;
        S_s[dk*65 + dv] = g_S[(size_t)bc*4096 + idx];
    }
    __syncthreads();
    if (tid < 64) {
        float c = 0.f;
        for (int i = 0; i < 32; i++) { c += cum_s[i*65 + tid]; cum_s[i*65 + tid] = c; }
    }
    __syncthreads();
    if (tid < 32) {
        float s = 0.f;
        #pragma unroll
        for (int d = 0; d < 64; d++)
            s += r_s[tid*65 + d] * __ldg(&faaaa[d]) * k_s[tid*65 + d];
        diag_s[tid] = s;
    }
    __syncthreads();
    for (int idx = tid; idx < 2048; idx += 256) {
        int i = idx >> 6, d = idx & 63;
        float ce = (i == 0) ? 0.f : cum_s[(i-1)*65 + d];
        r_s[i*65 + d] *= expf(ce);
        k_s[i*65 + d] *= expf(-cum_s[i*65 + d]);
    }
    __syncthreads();
    #pragma unroll
    for (int q = 0; q < 4; q++) {
        int idx = tid + 256*q;
        int i = idx >> 5, j = idx & 31;
        float val;
        if (j < i) {
            float s = 0.f;
            #pragma unroll
            for (int d = 0; d < 64; d++)
                s += r_s[i*65 + d] * k_s[j*65 + d];
            val = s;
        } else {
            val = (j == i) ? diag_s[i] : 0.f;
        }
        sc_s[i*33 + j] = val;
    }
    __syncthreads();
    #pragma unroll
    for (int q = 0; q < 8; q++) {
        int idx = tid + 256*q;
        int i = idx >> 6, dv = idx & 63;
        float o = 0.f;
        #pragma unroll
        for (int j = 0; j < 32; j++)
            o += sc_s[i*33 + j] * v_s[j*65 + dv];
        #pragma unroll
        for (int d = 0; d < 64; d++)
            o += r_s[i*65 + d] * S_s[d*65 + dv];
        g_o[(size_t)tok0*64 + idx] = o;
    }
}

// =====================================================================
// K6 (proven): out = (o * g) @ W_o via tf32 mma, 128x128 tile
// =====================================================================
#define K6_SMEM_BYTES ((128*68 + 64*136)*4)
__global__ __launch_bounds__(256,1) void k6_out(
    const float* __restrict__ Wo, float* __restrict__ out)
{
    extern __shared__ float sm6[];
    float* a_s = sm6;
    float* b_s = a_s + 128*68;

    const int tid  = threadIdx.x;
    const int lane = tid & 31, wid = tid >> 5;
    const int gi   = lane >> 2, t = lane & 3;
    const int bm = blockIdx.x * 128, bn = blockIdx.y * 128;

    for (int idx = tid; idx < 8192; idx += 256) {
        int i = idx >> 6, d = idx & 63;
        size_t g = (size_t)(bm+i)*64 + d;
        a_s[i*68 + d] = tf32r(g_o[g] * g_gv[g]);
    }
    for (int idx = tid; idx < 8192; idx += 256) {
        int dd = idx >> 7, n = idx & 127;
        b_s[dd*136 + n] = tf32r(Wo[(size_t)dd*CC + bn + n]);
    }
    __syncthreads();

    const int rb = (wid & 3) * 32;
    const int n0 = (wid >> 2) * 64;
    float acc[2][8][4];
    #pragma unroll
    for (int mi = 0; mi < 2; mi++)
        #pragma unroll
        for (int j = 0; j < 8; j++)
            #pragma unroll
            for (int e = 0; e < 4; e++) acc[mi][j][e] = 0.f;

    #pragma unroll
    for (int ks = 0; ks < 8; ks++) {
        unsigned a[2][4];
        #pragma unroll
        for (int mi = 0; mi < 2; mi++) {
            const float* Ab = a_s + (rb + mi*16)*68 + ks*8;
            a[mi][0] = FB(Ab[gi*68 + t]);
            a[mi][1] = FB(Ab[(gi+8)*68 + t]);
            a[mi][2] = FB(Ab[gi*68 + t + 4]);
            a[mi][3] = FB(Ab[(gi+8)*68 + t + 4]);
        }
        #pragma unroll
        for (int j = 0; j < 8; j++) {
            unsigned b0 = FB(b_s[(ks*8+t)*136 + n0 + j*8 + gi]);
            unsigned b1 = FB(b_s[(ks*8+t+4)*136 + n0 + j*8 + gi]);
            mma8(acc[0][j], a[0][0],a[0][1],a[0][2],a[0][3], b0,b1);
            mma8(acc[1][j], a[1][0],a[1][1],a[1][2],a[1][3], b0,b1);
        }
    }
    #pragma unroll
    for (int mi = 0; mi < 2; mi++)
        #pragma unroll
        for (int j = 0; j < 8; j++) {
            int m = bm + rb + mi*16 + gi;
            int n = bn + n0 + j*8 + t*2;
            out[(size_t)m*CC + n]       = acc[mi][j][0];
            out[(size_t)m*CC + n + 1]   = acc[mi][j][1];
            out[(size_t)(m+8)*CC + n]   = acc[mi][j][2];
            out[(size_t)(m+8)*CC + n+1] = acc[mi][j][3];
        }
}

// =====================================================================
extern "C" void kernel_launch(void* const* d_in, const int* in_sizes, int n_in,
                              void* d_out, int out_size)
{
    (void)in_sizes; (void)n_in; (void)out_size;
    const float* hs     = (const float*)d_in[0];
    const float* shift  = (const float*)d_in[1];
    const float* wkv0   = (const float*)d_in[2];
    const float* maa_x  = (const float*)d_in[3];
    const float* maa_w  = (const float*)d_in[4];
    const float* maa_k  = (const float*)d_in[5];
    const float* maa_v  = (const float*)d_in[6];
    const float* maa_r  = (const float*)d_in[7];
    const float* maa_g  = (const float*)d_in[8];
    const float* w1     = (const float*)d_in[9];
    const float* w2     = (const float*)d_in[10];
    const float* tdecay = (const float*)d_in[11];
    const float* dw1    = (const float*)d_in[12];
    const float* dw2    = (const float*)d_in[13];
    const float* faaaa  = (const float*)d_in[14];
    const float* Wr     = (const float*)d_in[15];
    const float* Wk     = (const float*)d_in[16];
    const float* Wv     = (const float*)d_in[17];
    const float* Wg     = (const float*)d_in[18];
    const float* Wo     = (const float*)d_in[19];
    float* out = (float*)d_out;

    const size_t OFF_LX = (size_t)BQ*TT*CC;
    const size_t OFF_SF = OFF_LX + (size_t)BQ*CC;

    cudaFuncSetAttribute(k1_mix,   cudaFuncAttributeMaxDynamicSharedMemorySize, K1_SMEM_BYTES);
    cudaFuncSetAttribute(kp_proj,  cudaFuncAttributeMaxDynamicSharedMemorySize, KP_SMEM_BYTES);
    cudaFuncSetAttribute(k5_intra, cudaFuncAttributeMaxDynamicSharedMemorySize, K5_SMEM_BYTES);
    cudaFuncSetAttribute(k6_out,   cudaFuncAttributeMaxDynamicSharedMemorySize, K6_SMEM_BYTES);

    // k1 at ncu's sampled launch index 3.
    kprep1  <<<256, 256>>>(w1);                                    // idx 0
    kprep2  <<<512, 256>>>(w2, dw1, Wk, Wv, Wr, Wg);               // idx 1
    k7_lx   <<<8, 512>>>(hs, out + OFF_LX);                        // idx 2
    k1_mix  <<<MTOK/32, 256, K1_SMEM_BYTES>>>(hs, shift, maa_x);   // idx 3
    kp_proj <<<dim3(MTOK/128, 5), 256, KP_SMEM_BYTES>>>(hs, shift, // idx 4
                                                        maa_w, maa_k, maa_v,
                                                        maa_r, maa_g,
                                                        dw2, tdecay);
    k3_chunk<<<BQ*NCH, 256>>>();                                   // idx 5
    k4_scan <<<32, 256>>>(wkv0, out + OFF_SF);                     // idx 6
    k5_intra<<<BQ*NCH, 256, K5_SMEM_BYTES>>>(faaaa);               // idx 7
    k6_out  <<<dim3(MTOK/128, CC/128), 256, K6_SMEM_BYTES>>>(Wo, out);  // idx 8
}

// round 16
// speedup vs baseline: 1.6632x; 1.0280x over previous
#include <cuda_runtime.h>
#include <math.h>

// Problem constants
#define BQ   2
#define TT   4096
#define CC   2048
#define DD   64
#define MTOK (BQ*TT)      // 8192 tokens
#define LCH  32
#define NCH  (TT/LCH)     // 128 chunks per batch

// ---------------- device scratch ----------------
__device__ __align__(16) float g_y  [MTOK*160];      // tanh mix features (tf32-rounded)
__device__ __align__(16) float g_w1p[CC*160];        // w1, pair-packed per 32-chunk
__device__ __align__(16) float g_w2p[160*CC];        // w2, pair-packed
__device__ __align__(16) float g_Wp [5*CC*DD];       // {dw1,Wk,Wv,Wr,Wg}, pair-packed
__device__ __align__(16) float g_r [MTOK*DD];
__device__ __align__(16) float g_k [MTOK*DD];
__device__ __align__(16) float g_v [MTOK*DD];
__device__ __align__(16) float g_gv[MTOK*DD];
__device__ __align__(16) float g_w [MTOK*DD];
__device__ __align__(16) float g_M [BQ*NCH*DD*DD];
__device__ __align__(16) float g_S [BQ*NCH*DD*DD];
__device__ __align__(16) float g_P [BQ*NCH*DD];
__device__ __align__(16) float g_o [MTOK*DD];

// ---------------- helpers ----------------
__device__ __forceinline__ float tf32r(float x) {
    unsigned u;
    asm("cvt.rna.tf32.f32 %0, %1;" : "=r"(u) : "f"(x));
    return __uint_as_float(u);
}
__device__ __forceinline__ void mma8(float* d,
    unsigned a0, unsigned a1, unsigned a2, unsigned a3,
    unsigned b0, unsigned b1)
{
    asm volatile(
        "mma.sync.aligned.m16n8k8.row.col.f32.tf32.tf32.f32 "
        "{%0,%1,%2,%3}, {%4,%5,%6,%7}, {%8,%9}, {%0,%1,%2,%3};"
        : "+f"(d[0]), "+f"(d[1]), "+f"(d[2]), "+f"(d[3])
        : "r"(a0), "r"(a1), "r"(a2), "r"(a3), "r"(b0), "r"(b1));
}
__device__ __forceinline__ void cpa16(unsigned dst, const float* src) {
    asm volatile("cp.async.ca.shared.global [%0], [%1], 16;" :: "r"(dst), "l"(src));
}
#define CPA_COMMIT() asm volatile("cp.async.commit_group;")
#define CPA_WAIT0()  asm volatile("cp.async.wait_group 0;")
#define FB(x) __float_as_uint(x)

// pair decode: pair index p=(ks*4+t), h in {0,1} -> k_local = ks*8+t+4h
__device__ __forceinline__ int pair_kl(int p, int h) {
    return (p >> 2)*8 + (p & 3) + 4*h;
}

// =====================================================================
// KPREP: tf32-round + pair-pack all weights, chunk-contiguous.
//  g_w1p[c][n][q]  : c<64 chunks, n<160, q = p*2+h (32)     (src w1[k][n])
//  g_w2p[f][c][cl][q]: f<5, c<64, cl<32, q<32              (src w2[f*32+d][c*32+cl], k-dim = d)
//  g_Wp [f][c][n][q] : f<5, c<64, n<64, q<32               (src Wf[k][n])
// =====================================================================
__global__ __launch_bounds__(256) void kprep(
    const float* __restrict__ w1,  const float* __restrict__ w2,
    const float* __restrict__ dw1, const float* __restrict__ Wk,
    const float* __restrict__ Wv,  const float* __restrict__ Wr_,
    const float* __restrict__ Wg)
{
    int i0 = blockIdx.x*256 + threadIdx.x;
    for (int dst = i0; dst < CC*160; dst += gridDim.x*256) {
        int c = dst / 5120, r = dst - c*5120;
        int n = r >> 5, q = r & 31, p = q >> 1, h = q & 1;
        int k = c*32 + pair_kl(p, h);
        g_w1p[dst] = tf32r(w1[(size_t)k*160 + n]);
    }
    for (int dst = i0; dst < 160*CC; dst += gridDim.x*256) {
        int f = dst >> 16, r = dst & 65535;
        int c = r >> 10, r2 = r & 1023;
        int cl = r2 >> 5, q = r2 & 31, p = q >> 1, h = q & 1;
        int d = pair_kl(p, h);
        g_w2p[dst] = tf32r(w2[(size_t)(f*32 + d)*CC + c*32 + cl]);
    }
    for (int dst = i0; dst < 5*CC*DD; dst += gridDim.x*256) {
        int f = dst / 131072, r = dst - f*131072;
        int c = r >> 11, r2 = r & 2047;
        int n = r2 >> 5, q = r2 & 31, p = q >> 1, h = q & 1;
        int k = c*32 + pair_kl(p, h);
        const float* Wf = (f==0) ? dw1 : (f==1) ? Wk : (f==2) ? Wv
                         : (f==3) ? Wr_ : Wg;
        g_Wp[dst] = tf32r(Wf[(size_t)k*64 + n]);
    }
}

// =====================================================================
// K7: lx = hs[:, -1, :]
// =====================================================================
__global__ void k7_lx(const float* __restrict__ hs, float* __restrict__ out_lx)
{
    int idx = blockIdx.x*blockDim.x + threadIdx.x;   // B*C = 4096
    int b = idx >> 11, c = idx & 2047;
    out_lx[idx] = hs[((size_t)b*TT + (TT-1))*CC + c];
}

// =====================================================================
// K1 v4: cp.async double-buffered + pair-packed w1 (float2 B-frags)
// Stage (floats): hs[33*36]=1188 | w1p[160][40]=6400 | maa[32] -> 7620.
// smem = 2*7620*4 = 60960 B -> 3 blocks/SM.
// =====================================================================
#define K1_SSTR  7620
#define K1_SMEM_BYTES (2*K1_SSTR*4)

__global__ __launch_bounds__(256,3) void k1_mix(
    const float* __restrict__ hs, const float* __restrict__ shift,
    const float* __restrict__ maa_x)
{
    extern __shared__ float sm1[];
    float* stg = sm1;

    const int tid  = threadIdx.x;
    const int lane = tid & 31, wid = tid >> 5;
    const int gi   = lane >> 2, t = lane & 3;
    const int m0   = blockIdx.x * 32;
    const int mt   = wid & 1;          // 16-row tile
    const int ng   = wid >> 1;         // col group of 40

    const unsigned stg_sh = (unsigned)__cvta_generic_to_shared(stg);

    auto issue_stage = [&](int s, int cch) {    // cch = chunk index
        unsigned hb = stg_sh + (unsigned)(s*K1_SSTR)*4u;
        const int k0n = cch*32;
        for (int idx = tid; idx < 264; idx += 256) {
            int i = idx >> 3, c4 = (idx & 7) << 2;
            const float* src;
            if (i == 0 && (m0 & (TT-1)) == 0)
                src = shift + (size_t)(m0 >> 12)*CC + k0n + c4;
            else
                src = hs + (size_t)(m0 - 1 + i)*CC + k0n + c4;
            cpa16(hb + (unsigned)(i*36 + c4)*4u, src);
        }
        // w1p chunk: 5120 contiguous floats -> [n][40] padded
        for (int idx = tid; idx < 1280; idx += 256) {
            int n = idx >> 3, o4 = (idx & 7) << 2;
            cpa16(hb + (unsigned)(1188 + n*40 + o4)*4u,
                  g_w1p + (size_t)cch*5120 + idx*4);
        }
        if (tid < 8)
            cpa16(hb + (unsigned)(7588 + tid*4)*4u, maa_x + k0n + tid*4);
    };

    issue_stage(0, 0);
    CPA_COMMIT();

    float acc[5][4];
    #pragma unroll
    for (int j = 0; j < 5; j++)
        #pragma unroll
        for (int e = 0; e < 4; e++) acc[j][e] = 0.f;

    const int r0 = mt*16 + gi;
    const int r1 = r0 + 8;

    for (int n = 0; n < 64; n++) {
        const int s = n & 1;
        float* hs_s  = stg + s*K1_SSTR;
        float* w1p_s = hs_s + 1188;
        float* maa_s = hs_s + 7588;

        CPA_WAIT0();
        __syncthreads();
        if (n < 63) issue_stage(s ^ 1, n + 1);
        CPA_COMMIT();

        #pragma unroll
        for (int ks = 0; ks < 4; ks++) {
            int cl0 = ks*8 + t, cl1 = cl0 + 4;
            float ma0 = maa_s[cl0];
            float ma1 = maa_s[cl1];
            float c00 = hs_s[(r0+1)*36 + cl0], p00 = hs_s[r0*36 + cl0];
            float c10 = hs_s[(r1+1)*36 + cl0], p10 = hs_s[r1*36 + cl0];
            float c01 = hs_s[(r0+1)*36 + cl1], p01 = hs_s[r0*36 + cl1];
            float c11 = hs_s[(r1+1)*36 + cl1], p11 = hs_s[r1*36 + cl1];
            unsigned a0 = FB(tf32r(c00 + (p00 - c00) * ma0));
            unsigned a1 = FB(tf32r(c10 + (p10 - c10) * ma0));
            unsigned a2 = FB(tf32r(c01 + (p01 - c01) * ma1));
            unsigned a3 = FB(tf32r(c11 + (p11 - c11) * ma1));
            const int pq = (ks*4 + t)*2;
            #pragma unroll
            for (int j = 0; j < 5; j++) {
                int nn = ng*40 + j*8 + gi;
                float2 b01 = *(const float2*)(w1p_s + nn*40 + pq);
                mma8(acc[j], a0,a1,a2,a3, FB(b01.x), FB(b01.y));
            }
        }
    }
    const int mrow = m0 + mt*16 + gi;
    #pragma unroll
    for (int j = 0; j < 5; j++) {
        int n = ng*40 + j*8 + t*2;
        g_y[(size_t)mrow*160 + n]       = tf32r(tanhf(acc[j][0]));
        g_y[(size_t)mrow*160 + n + 1]   = tf32r(tanhf(acc[j][1]));
        g_y[(size_t)(mrow+8)*160 + n]   = tf32r(tanhf(acc[j][2]));
        g_y[(size_t)(mrow+8)*160 + n+1] = tf32r(tanhf(acc[j][3]));
    }
}

// =====================================================================
// KP v6: cp.async + pair-packed w2/W (float2 B-frags), shuffle A-frags.
// Stage (floats): hs[129*36]=4644 | w2p[32][40]=1280 | Wp[64][40]=2560
//                 | maa[32] -> stride 8516. 2 stages = 68128 B.
// =====================================================================
#define KP_SSTR  8516
#define KP_SMEM_FLOATS (2*KP_SSTR)
#define KP_SMEM_BYTES  (KP_SMEM_FLOATS*4)

__global__ __launch_bounds__(256,3) void kp_proj(
    const float* __restrict__ hs, const float* __restrict__ shift,
    const float* __restrict__ maa_w, const float* __restrict__ maa_k,
    const float* __restrict__ maa_v, const float* __restrict__ maa_r,
    const float* __restrict__ maa_g,
    const float* __restrict__ dw2,   const float* __restrict__ tdecay)
{
    extern __shared__ float sm[];
    float* stg = sm;

    const int tid  = threadIdx.x;
    const int lane = tid & 31, wid = tid >> 5;
    const int gi   = lane >> 2, t = lane & 3;
    const int m0   = blockIdx.x * 128;
    const int f    = blockIdx.y;

    const float* mp = (f==0) ? maa_w : (f==1) ? maa_k : (f==2) ? maa_v
                     : (f==3) ? maa_r : maa_g;

    const unsigned stg_sh = (unsigned)__cvta_generic_to_shared(stg);

    auto issue_stage = [&](int s, int cch) {
        unsigned hb = stg_sh + (unsigned)(s*KP_SSTR)*4u;
        const int c0n = cch*32;
        for (int idx = tid; idx < 1032; idx += 256) {
            int i = idx >> 3, c4 = (idx & 7) << 2;
            const float* src;
            if (i == 0 && (m0 & (TT-1)) == 0)
                src = shift + (size_t)(m0 >> 12)*CC + c0n + c4;
            else
                src = hs + (size_t)(m0 - 1 + i)*CC + c0n + c4;
            cpa16(hb + (unsigned)(i*36 + c4)*4u, src);
        }
        // w2p: 1024 contiguous floats -> [cl][40]
        {
            int cl = tid >> 3, o4 = (tid & 7) << 2;   // tid < 256 exactly
            cpa16(hb + (unsigned)(4644 + cl*40 + o4)*4u,
                  g_w2p + ((size_t)f*64 + cch)*1024 + tid*4);
        }
        // Wp: 2048 contiguous floats -> [n][40]
        #pragma unroll
        for (int u = 0; u < 2; u++) {
            int idx = tid + u*256;
            int n = idx >> 3, o4 = (idx & 7) << 2;
            cpa16(hb + (unsigned)(5924 + n*40 + o4)*4u,
                  g_Wp + ((size_t)f*64 + cch)*2048 + idx*4);
        }
        if (tid < 8)
            cpa16(hb + (unsigned)(8484 + tid*4)*4u, mp + c0n + tid*4);
    };

    issue_stage(0, 0);
    CPA_COMMIT();
    {
        float* ytmp = stg + KP_SSTR;     // borrowed; dead after extraction
        for (int idx = tid; idx < 128*32; idx += 256) {
            int i = idx >> 5, kk = idx & 31;
            ytmp[i*36 + kk] = g_y[(size_t)(m0+i)*160 + f*32 + kk];
        }
        __syncthreads();
    }
    unsigned ya[4][4];
    {
        float* ytmp = stg + KP_SSTR;
        #pragma unroll
        for (int ks = 0; ks < 4; ks++) {
            const float* Ab = ytmp + (wid*16)*36 + ks*8;
            ya[ks][0] = FB(Ab[gi*36 + t]);
            ya[ks][1] = FB(Ab[(gi+8)*36 + t]);
            ya[ks][2] = FB(Ab[gi*36 + t + 4]);
            ya[ks][3] = FB(Ab[(gi+8)*36 + t + 4]);
        }
    }

    const int p  = t & 1;
    const int s0 = (lane & ~3) | (t >> 1);
    const int s4 = s0 + 2;

    float acc[8][4];
    #pragma unroll
    for (int j = 0; j < 8; j++)
        #pragma unroll
        for (int e = 0; e < 4; e++) acc[j][e] = 0.f;

    for (int n = 0; n < 64; n++) {
        const int s = n & 1;
        float* hs_s  = stg + s*KP_SSTR;
        float* w2p_s = hs_s + 4644;
        float* Wp_s  = hs_s + 5924;
        float* maa_s = hs_s + 8484;

        CPA_WAIT0();
        __syncthreads();
        if (n < 63) issue_stage(s ^ 1, n + 1);
        CPA_COMMIT();

        // phase A: m = y @ w2 (pair-packed B)
        float av[4][4];
        #pragma unroll
        for (int j = 0; j < 4; j++)
            #pragma unroll
            for (int e = 0; e < 4; e++) av[j][e] = 0.f;
        #pragma unroll
        for (int ks = 0; ks < 4; ks++) {
            const int pq = (ks*4 + t)*2;
            #pragma unroll
            for (int j = 0; j < 4; j++) {
                float2 b01 = *(const float2*)(w2p_s + (j*8 + gi)*40 + pq);
                mma8(av[j], ya[ks][0], ya[ks][1], ya[ks][2], ya[ks][3],
                     FB(b01.x), FB(b01.y));
            }
        }
        // A build in registers (C-frag layout), tf32-rounded
        #pragma unroll
        for (int j = 0; j < 4; j++) {
            #pragma unroll
            for (int e = 0; e < 4; e++) {
                int r = wid*16 + gi + ((e & 2) ? 8 : 0);
                int c = j*8 + t*2 + (e & 1);
                float cur  = hs_s[(r+1)*36 + c];
                float prev = hs_s[r*36 + c];
                av[j][e] = tf32r(cur + (prev - cur)*(maa_s[c] + av[j][e]));
            }
        }

        // phase B: acc += A @ W ; A-frags via shuffle, B pair-packed
        #pragma unroll
        for (int ks = 0; ks < 4; ks++) {
            float v00 = __shfl_sync(0xffffffffu, av[ks][0], s0);
            float v01 = __shfl_sync(0xffffffffu, av[ks][1], s0);
            float v02 = __shfl_sync(0xffffffffu, av[ks][2], s0);
            float v03 = __shfl_sync(0xffffffffu, av[ks][3], s0);
            float v40 = __shfl_sync(0xffffffffu, av[ks][0], s4);
            float v41 = __shfl_sync(0xffffffffu, av[ks][1], s4);
            float v42 = __shfl_sync(0xffffffffu, av[ks][2], s4);
            float v43 = __shfl_sync(0xffffffffu, av[ks][3], s4);
            unsigned a0 = FB(p ? v01 : v00);
            unsigned a1 = FB(p ? v03 : v02);
            unsigned a2 = FB(p ? v41 : v40);
            unsigned a3 = FB(p ? v43 : v42);
            const int pq = (ks*4 + t)*2;
            #pragma unroll
            for (int j = 0; j < 8; j++) {
                float2 b01 = *(const float2*)(Wp_s + (j*8 + gi)*40 + pq);
                mma8(acc[j], a0,a1,a2,a3, FB(b01.x), FB(b01.y));
            }
        }
    }

    if (f != 0) {
        #pragma unroll
        for (int j = 0; j < 8; j++) {
            #pragma unroll
            for (int e = 0; e < 4; e++) {
                int m = m0 + wid*16 + gi + ((e & 2) ? 8 : 0);
                int nn = j*8 + t*2 + (e & 1);
                size_t ad = (size_t)m*64 + nn;
                float x = acc[j][e];
                if      (f == 1) g_k[ad] = x;
                else if (f == 2) g_v[ad] = x;
                else if (f == 3) g_r[ad] = x;
                else             g_gv[ad] = x / (1.f + expf(-x));
            }
        }
    } else {
        // folded decay: T = tf32(tanh(acc)); g_w = -exp(tdecay + T@dw2)
        __syncthreads();
        float* T_s  = sm;                // [128][68] = 8704
        float* d2_s = sm + 8704;         // [64][72]  = 4608
        float* td_s = sm + 13312;        // [64]
        #pragma unroll
        for (int j = 0; j < 8; j++) {
            #pragma unroll
            for (int e = 0; e < 4; e++) {
                int r = wid*16 + gi + ((e & 2) ? 8 : 0);
                int c = j*8 + t*2 + (e & 1);
                T_s[r*68 + c] = tf32r(tanhf(acc[j][e]));
            }
        }
        for (int idx = tid; idx < 4096; idx += 256) {
            int d = idx >> 6, nn = idx & 63;
            d2_s[d*72 + nn] = tf32r(dw2[idx]);
        }
        if (tid < 64) td_s[tid] = tdecay[tid];
        __syncthreads();

        float acc2[8][4];
        #pragma unroll
        for (int j = 0; j < 8; j++)
            #pragma unroll
            for (int e = 0; e < 4; e++) acc2[j][e] = 0.f;
        #pragma unroll
        for (int ks = 0; ks < 8; ks++) {
            const float* Ab = T_s + (wid*16)*68 + ks*8;
            unsigned a0 = FB(Ab[gi*68 + t]);
            unsigned a1 = FB(Ab[(gi+8)*68 + t]);
            unsigned a2 = FB(Ab[gi*68 + t + 4]);
            unsigned a3 = FB(Ab[(gi+8)*68 + t + 4]);
            #pragma unroll
            for (int j = 0; j < 8; j++) {
                unsigned b0 = FB(d2_s[(ks*8+t)*72 + j*8 + gi]);
                unsigned b1 = FB(d2_s[(ks*8+t+4)*72 + j*8 + gi]);
                mma8(acc2[j], a0,a1,a2,a3, b0,b1);
            }
        }
        #pragma unroll
        for (int j = 0; j < 8; j++) {
            #pragma unroll
            for (int e = 0; e < 4; e++) {
                int m = m0 + wid*16 + gi + ((e & 2) ? 8 : 0);
                int nn = j*8 + t*2 + (e & 1);
                g_w[(size_t)m*64 + nn] = -expf(td_s[nn] + acc2[j][e]);
            }
        }
    }
}

// =====================================================================
// K3 (proven)
// =====================================================================
__global__ __launch_bounds__(256,1) void k3_chunk()
{
    __shared__ float k_s[32*64], v_s[32*64], cum_s[32*64], kh_s[32*64];
    const int bc   = blockIdx.x;
    const int tok0 = bc * 32;
    const int tid  = threadIdx.x;

    for (int idx = tid; idx < 2048; idx += 256) {
        size_t g = (size_t)tok0*64 + idx;
        k_s[idx]   = g_k[g];
        v_s[idx]   = g_v[g];
        cum_s[idx] = g_w[g];
    }
    __syncthreads();
    if (tid < 64) {
        float c = 0.f;
        for (int i = 0; i < 32; i++) { c += cum_s[i*64 + tid]; cum_s[i*64 + tid] = c; }
        g_P[bc*64 + tid] = expf(c);
        for (int i = 0; i < 32; i++)
            kh_s[i*64 + tid] = k_s[i*64 + tid] * expf(c - cum_s[i*64 + tid]);
    }
    __syncthreads();
    for (int it = 0; it < 16; it++) {
        int e  = tid + 256*it;
        int dk = e >> 6, dv = e & 63;
        float s = 0.f;
        #pragma unroll
        for (int i = 0; i < 32; i++)
            s += kh_s[i*64 + dk] * v_s[i*64 + dv];
        g_M[(size_t)bc*4096 + e] = s;
    }
}

// =====================================================================
// K4 (proven): inter-chunk scan, prefetch depth 32
// =====================================================================
__global__ __launch_bounds__(256,1) void k4_scan(
    const float* __restrict__ wkv0, float* __restrict__ out_sf)
{
    const int e  = blockIdx.x*256 + threadIdx.x;
    const int b  = e >> 12, eb = e & 4095, dk = eb >> 6;
    float sv = wkv0[e];
    const float* Mp = g_M + (size_t)b*NCH*4096 + eb;
    const float* Pp = g_P + b*NCH*64 + dk;
    float*       Sp = g_S + (size_t)b*NCH*4096 + eb;

    float mq[32], pq[32];
    #pragma unroll
    for (int q = 0; q < 32; q++) { mq[q] = Mp[(size_t)q*4096]; pq[q] = Pp[q*64]; }

    for (int c = 0; c < NCH; c += 32) {
        #pragma unroll
        for (int q = 0; q < 32; q++) {
            Sp[(size_t)(c+q)*4096] = sv;
            sv = sv*pq[q] + mq[q];
            int cn = c + q + 32;
            if (cn < NCH) { mq[q] = Mp[(size_t)cn*4096]; pq[q] = Pp[cn*64]; }
        }
    }
    out_sf[e] = sv;
}

// =====================================================================
// K5 (proven)
// =====================================================================
#define K5_SMEM_FLOATS (4*(32*65) + 64*65 + 32*33 + 32)
#define K5_SMEM_BYTES  (K5_SMEM_FLOATS*4)

__global__ __launch_bounds__(256,1) void k5_intra(const float* __restrict__ faaaa)
{
    extern __shared__ float sm5[];
    float* r_s    = sm5;
    float* k_s    = r_s   + 32*65;
    float* v_s    = k_s   + 32*65;
    float* cum_s  = v_s   + 32*65;
    float* S_s    = cum_s + 32*65;
    float* sc_s   = S_s   + 64*65;
    float* diag_s = sc_s  + 32*33;

    const int bc   = blockIdx.x;
    const int tok0 = bc * 32;
    const int tid  = threadIdx.x;

    for (int idx = tid; idx < 2048; idx += 256) {
        int i = idx >> 6, d = idx & 63;
        size_t g = (size_t)tok0*64 + idx;
        r_s[i*65 + d]   = g_r[g];
        k_s[i*65 + d]   = g_k[g];
        v_s[i*65 + d]   = g_v[g];
        cum_s[i*65 + d] = g_w[g];
    }
    for (int idx = tid; idx < 4096; idx += 256) {
        int dk = idx >> 6, dv = idx & 63;
        S_s[dk*65 + dv] = g_S[(size_t)bc*4096 + idx];
    }
    __syncthreads();
    if (tid < 64) {
        float c = 0.f;
        for (int i = 0; i < 32; i++) { c += cum_s[i*65 + tid]; cum_s[i*65 + tid] = c; }
    }
    __syncthreads();
    if (tid < 32) {
        float s = 0.f;
        #pragma unroll
        for (int d = 0; d < 64; d++)
            s += r_s[tid*65 + d] * __ldg(&faaaa[d]) * k_s[tid*65 + d];
        diag_s[tid] = s;
    }
    __syncthreads();
    for (int idx = tid; idx < 2048; idx += 256) {
        int i = idx >> 6, d = idx & 63;
        float ce = (i == 0) ? 0.f : cum_s[(i-1)*65 + d];
        r_s[i*65 + d] *= expf(ce);
        k_s[i*65 + d] *= expf(-cum_s[i*65 + d]);
    }
    __syncthreads();
    #pragma unroll
    for (int q = 0; q < 4; q++) {
        int idx = tid + 256*q;
        int i = idx >> 5, j = idx & 31;
        float val;
        if (j < i) {
            float s = 0.f;
            #pragma unroll
            for (int d = 0; d < 64; d++)
                s += r_s[i*65 + d] * k_s[j*65 + d];
            val = s;
        } else {
            val = (j == i) ? diag_s[i] : 0.f;
        }
        sc_s[i*33 + j] = val;
    }
    __syncthreads();
    #pragma unroll
    for (int q = 0; q < 8; q++) {
        int idx = tid + 256*q;
        int i = idx >> 6, dv = idx & 63;
        float o = 0.f;
        #pragma unroll
        for (int j = 0; j < 32; j++)
            o += sc_s[i*33 + j] * v_s[j*65 + dv];
        #pragma unroll
        for (int d = 0; d < 64; d++)
            o += r_s[i*65 + d] * S_s[d*65 + dv];
        g_o[(size_t)tok0*64 + idx] = o;
    }
}

// =====================================================================
// K6 (proven): out = (o * g) @ W_o via tf32 mma, 128x128 tile
// =====================================================================
#define K6_SMEM_BYTES ((128*68 + 64*136)*4)
__global__ __launch_bounds__(256,1) void k6_out(
    const float* __restrict__ Wo, float* __restrict__ out)
{
    extern __shared__ float sm6[];
    float* a_s = sm6;
    float* b_s = a_s + 128*68;

    const int tid  = threadIdx.x;
    const int lane = tid & 31, wid = tid >> 5;
    const int gi   = lane >> 2, t = lane & 3;
    const int bm = blockIdx.x * 128, bn = blockIdx.y * 128;

    for (int idx = tid; idx < 8192; idx += 256) {
        int i = idx >> 6, d = idx & 63;
        size_t g = (size_t)(bm+i)*64 + d;
        a_s[i*68 + d] = tf32r(g_o[g] * g_gv[g]);
    }
    for (int idx = tid; idx < 8192; idx += 256) {
        int dd = idx >> 7, n = idx & 127;
        b_s[dd*136 + n] = tf32r(Wo[(size_t)dd*CC + bn + n]);
    }
    __syncthreads();

    const int rb = (wid & 3) * 32;
    const int n0 = (wid >> 2) * 64;
    float acc[2][8][4];
    #pragma unroll
    for (int mi = 0; mi < 2; mi++)
        #pragma unroll
        for (int j = 0; j < 8; j++)
            #pragma unroll
            for (int e = 0; e < 4; e++) acc[mi][j][e] = 0.f;

    #pragma unroll
    for (int ks = 0; ks < 8; ks++) {
        unsigned a[2][4];
        #pragma unroll
        for (int mi = 0; mi < 2; mi++) {
            const float* Ab = a_s + (rb + mi*16)*68 + ks*8;
            a[mi][0] = FB(Ab[gi*68 + t]);
            a[mi][1] = FB(Ab[(gi+8)*68 + t]);
            a[mi][2] = FB(Ab[gi*68 + t + 4]);
            a[mi][3] = FB(Ab[(gi+8)*68 + t + 4]);
        }
        #pragma unroll
        for (int j = 0; j < 8; j++) {
            unsigned b0 = FB(b_s[(ks*8+t)*136 + n0 + j*8 + gi]);
            unsigned b1 = FB(b_s[(ks*8+t+4)*136 + n0 + j*8 + gi]);
            mma8(acc[0][j], a[0][0],a[0][1],a[0][2],a[0][3], b0,b1);
            mma8(acc[1][j], a[1][0],a[1][1],a[1][2],a[1][3], b0,b1);
        }
    }
    #pragma unroll
    for (int mi = 0; mi < 2; mi++)
        #pragma unroll
        for (int j = 0; j < 8; j++) {
            int m = bm + rb + mi*16 + gi;
            int n = bn + n0 + j*8 + t*2;
            out[(size_t)m*CC + n]       = acc[mi][j][0];
            out[(size_t)m*CC + n + 1]   = acc[mi][j][1];
            out[(size_t)(m+8)*CC + n]   = acc[mi][j][2];
            out[(size_t)(m+8)*CC + n+1] = acc[mi][j][3];
        }
}

// =====================================================================
extern "C" void kernel_launch(void* const* d_in, const int* in_sizes, int n_in,
                              void* d_out, int out_size)
{
    (void)in_sizes; (void)n_in; (void)out_size;
    const float* hs     = (const float*)d_in[0];
    const float* shift  = (const float*)d_in[1];
    const float* wkv0   = (const float*)d_in[2];
    const float* maa_x  = (const float*)d_in[3];
    const float* maa_w  = (const float*)d_in[4];
    const float* maa_k  = (const float*)d_in[5];
    const float* maa_v  = (const float*)d_in[6];
    const float* maa_r  = (const float*)d_in[7];
    const float* maa_g  = (const float*)d_in[8];
    const float* w1     = (const float*)d_in[9];
    const float* w2     = (const float*)d_in[10];
    const float* tdecay = (const float*)d_in[11];
    const float* dw1    = (const float*)d_in[12];
    const float* dw2    = (const float*)d_in[13];
    const float* faaaa  = (const float*)d_in[14];
    const float* Wr     = (const float*)d_in[15];
    const float* Wk     = (const float*)d_in[16];
    const float* Wv     = (const float*)d_in[17];
    const float* Wg     = (const float*)d_in[18];
    const float* Wo     = (const float*)d_in[19];
    float* out = (float*)d_out;

    const size_t OFF_LX = (size_t)BQ*TT*CC;
    const size_t OFF_SF = OFF_LX + (size_t)BQ*CC;

    cudaFuncSetAttribute(k1_mix,   cudaFuncAttributeMaxDynamicSharedMemorySize, K1_SMEM_BYTES);
    cudaFuncSetAttribute(kp_proj,  cudaFuncAttributeMaxDynamicSharedMemorySize, KP_SMEM_BYTES);
    cudaFuncSetAttribute(k5_intra, cudaFuncAttributeMaxDynamicSharedMemorySize, K5_SMEM_BYTES);
    cudaFuncSetAttribute(k6_out,   cudaFuncAttributeMaxDynamicSharedMemorySize, K6_SMEM_BYTES);

    // kp at ncu's sampled launch index 3.
    kprep   <<<512, 256>>>(w1, w2, dw1, Wk, Wv, Wr, Wg);           // idx 0
    k1_mix  <<<MTOK/32, 256, K1_SMEM_BYTES>>>(hs, shift, maa_x);   // idx 1
    k7_lx   <<<8, 512>>>(hs, out + OFF_LX);                        // idx 2
    kp_proj <<<dim3(MTOK/128, 5), 256, KP_SMEM_BYTES>>>(hs, shift, // idx 3
                                                        maa_w, maa_k, maa_v,
                                                        maa_r, maa_g,
                                                        dw2, tdecay);
    k3_chunk<<<BQ*NCH, 256>>>();                                   // idx 4
    k4_scan <<<32, 256>>>(wkv0, out + OFF_SF);                     // idx 5
    k5_intra<<<BQ*NCH, 256, K5_SMEM_BYTES>>>(faaaa);               // idx 6
    k6_out  <<<dim3(MTOK/128, CC/128), 256, K6_SMEM_BYTES>>>(Wo, out);  // idx 7
}